// round 13
// baseline (speedup 1.0000x reference)
#include <cuda_runtime.h>
#include <cuda_fp16.h>
#include <math.h>

// Problem constants
#define BATCH 8
#define NC    16
#define HH    320
#define WW    320
#define HW    102400
#define NITER 10
#define INIT_BLKS 100   // blocks/batch in k_init
#define UPD_BLKS  200   // blocks/batch in update kernels
#define SCALE_N2 (1.0f / 102400.0f)

// ---------------- scratch (device globals; no runtime allocation) ----------------
__device__ __align__(16) __half2 g_k[BATCH * NC * HW];   // coil k-space, fp16 complex (paired permuted layout)
__device__ __align__(16) __half2 g_csmh[BATCH * NC * HW];// csm fp16 complex, PAIRED layout per row
__device__ __align__(16) float2 g_x[BATCH * HW];
__device__ __align__(16) float2 g_r[BATCH * HW];
__device__ __align__(16) float2 g_p[BATCH * HW];
__device__ __align__(16) float2 g_Ap[BATCH * HW];
__device__ __align__(16) char2 g_maskPQ[BATCH * HW];    // (P, Q) pairs for fused mask stage
__device__ float  g_partPA[BATCH * HH];                 // p.Ap partials
__device__ float  g_partRR[BATCH * UPD_BLKS];           // r.r partials
__device__ float  g_partI[BATCH * INIT_BLKS];           // init rr partials
__device__ float  g_rTr[BATCH];
__device__ float  g_alpha[BATCH];
__device__ float  g_beta[BATCH];
__device__ unsigned g_cntPA[BATCH];                     // last-block counters (self-resetting)
__device__ unsigned g_cntRR[BATCH];
__device__ float2 g_tw320[288];           // exp(-2pi i k*lane/320), k=1..9
__device__ float2 g_tw32[128];            // fft32 stage twiddles; DOWN lanes hold (1,0)

// ---------------- complex helpers ----------------
__device__ __forceinline__ float2 cmul(float2 a, float2 b) {
    return make_float2(a.x*b.x - a.y*b.y, a.x*b.y + a.y*b.x);
}
__device__ __forceinline__ float2 cadd(float2 a, float2 b) { return make_float2(a.x+b.x, a.y+b.y); }
__device__ __forceinline__ float2 csub(float2 a, float2 b) { return make_float2(a.x-b.x, a.y-b.y); }
__device__ __forceinline__ int br5(int l) { return (int)(__brev((unsigned)l) >> 27); }

__device__ __forceinline__ unsigned pack_c(float2 v) {
    __half2 h = __floats2half2_rn(v.x, v.y);
    return *(unsigned*)&h;
}
__device__ __forceinline__ float2 unpack_c(unsigned u) {
    __half2 h = *(__half2*)&u;
    return __half22float2(h);
}

// ---------------- radix-5 ----------------
#define C51 0.30901699437494745f
#define C52 (-0.8090169943749475f)
#define S51 0.9510565162951535f
#define S52 0.5877852522924731f

template<int DIR>
__device__ __forceinline__ void fft5(float2 a0, float2 a1, float2 a2, float2 a3, float2 a4,
                                     float2& b0, float2& b1, float2& b2, float2& b3, float2& b4) {
    const float dir = (float)DIR;
    float2 t1 = cadd(a1, a4), t2 = cadd(a2, a3);
    float2 t3 = csub(a1, a4), t4 = csub(a2, a3);
    float2 m1 = make_float2(a0.x + C51*t1.x + C52*t2.x, a0.y + C51*t1.y + C52*t2.y);
    float2 m2 = make_float2(a0.x + C52*t1.x + C51*t2.x, a0.y + C52*t1.y + C51*t2.y);
    float2 u1 = make_float2(S51*t3.x + S52*t4.x, S51*t3.y + S52*t4.y);
    float2 u2 = make_float2(S52*t3.x - S51*t4.x, S52*t3.y - S51*t4.y);
    b0 = make_float2(a0.x + t1.x + t2.x, a0.y + t1.y + t2.y);
    b1 = make_float2(m1.x - dir*u1.y, m1.y + dir*u1.x);
    b4 = make_float2(m1.x + dir*u1.y, m1.y - dir*u1.x);
    b2 = make_float2(m2.x - dir*u2.y, m2.y + dir*u2.x);
    b3 = make_float2(m2.x + dir*u2.y, m2.y - dir*u2.x);
}

// ---------------- per-lane 10-point FFT ----------------
template<int DIR>
__device__ __forceinline__ void fft10(float2 v[10]) {
    const float dir = (float)DIR;
    float2 e0,e1,e2,e3,e4, o0,o1,o2,o3,o4;
    fft5<DIR>(v[0], v[2], v[4], v[6], v[8], e0, e1, e2, e3, e4);
    fft5<DIR>(v[1], v[3], v[5], v[7], v[9], o0, o1, o2, o3, o4);
    const float c1 = 0.80901699437494745f, s1 = 0.58778525229247314f;
    const float c2 = 0.30901699437494745f, s2 = 0.95105651629515357f;
    float2 t;
    v[0] = cadd(e0, o0);                       v[5] = csub(e0, o0);
    t = cmul(o1, make_float2( c1, dir*s1));    v[1] = cadd(e1, t); v[6] = csub(e1, t);
    t = cmul(o2, make_float2( c2, dir*s2));    v[2] = cadd(e2, t); v[7] = csub(e2, t);
    t = cmul(o3, make_float2(-c2, dir*s2));    v[3] = cadd(e3, t); v[8] = csub(e3, t);
    t = cmul(o4, make_float2(-c1, dir*s1));    v[4] = cadd(e4, t); v[9] = csub(e4, t);
}

// ---------------- full 320-pt forward; LAST=false skips final m=1 butterfly ----------------
// v[j]=x[lane+32j] -> lane holds X[10*br5(lane)+j] (when LAST=true)
template<bool LAST>
__device__ __forceinline__ void fft320_fwd_t(float2 v[10], int lane) {
    fft10<-1>(v);
    #pragma unroll
    for (int k = 1; k < 10; k++) v[k] = cmul(v[k], g_tw320[(k-1)*32 + lane]);
    #pragma unroll
    for (int s = 0; s < 4; s++) {
        int m = 16 >> s;
        float2 w = g_tw32[s*32 + lane];           // (1,0) on down lanes
        float sg = (lane & m) ? -1.f : 1.f;
        #pragma unroll
        for (int r = 0; r < 10; r++) {
            float ox = __shfl_xor_sync(0xffffffffu, v[r].x, m);
            float oy = __shfl_xor_sync(0xffffffffu, v[r].y, m);
            float tx = fmaf(sg, v[r].x, ox);
            float ty = fmaf(sg, v[r].y, oy);
            v[r] = cmul(make_float2(tx, ty), w);
        }
    }
    if (LAST) {
        float sg1 = (lane & 1) ? -1.f : 1.f;      // m=1: no twiddle
        #pragma unroll
        for (int r = 0; r < 10; r++) {
            float ox = __shfl_xor_sync(0xffffffffu, v[r].x, 1);
            float oy = __shfl_xor_sync(0xffffffffu, v[r].y, 1);
            v[r] = make_float2(fmaf(sg1, v[r].x, ox), fmaf(sg1, v[r].y, oy));
        }
    }
}
__device__ __forceinline__ void fft320_fwd(float2 v[10], int lane) { fft320_fwd_t<true>(v, lane); }

// ---------------- full 320-pt inverse (unnormalized); FIRST=false skips initial m=1 butterfly ----------------
template<bool FIRST>
__device__ __forceinline__ void fft320_inv_t(float2 v[10], int lane) {
    if (FIRST) {
        float sg1 = (lane & 1) ? -1.f : 1.f;      // m=1: no twiddle
        #pragma unroll
        for (int r = 0; r < 10; r++) {
            float ox = __shfl_xor_sync(0xffffffffu, v[r].x, 1);
            float oy = __shfl_xor_sync(0xffffffffu, v[r].y, 1);
            v[r] = make_float2(fmaf(sg1, v[r].x, ox), fmaf(sg1, v[r].y, oy));
        }
    }
    #pragma unroll
    for (int s = 3; s >= 0; s--) {
        int m = 16 >> s;
        float2 wf = g_tw32[s*32 + lane];
        float2 w = make_float2(wf.x, -wf.y);      // conj
        float sg = (lane & m) ? -1.f : 1.f;
        #pragma unroll
        for (int r = 0; r < 10; r++) {
            float2 u = cmul(v[r], w);             // pre-twiddle (unit on down lanes)
            float ox = __shfl_xor_sync(0xffffffffu, u.x, m);
            float oy = __shfl_xor_sync(0xffffffffu, u.y, m);
            v[r] = make_float2(fmaf(sg, u.x, ox), fmaf(sg, u.y, oy));
        }
    }
    #pragma unroll
    for (int k = 1; k < 10; k++) {
        float2 wf = g_tw320[(k-1)*32 + lane];
        v[k] = cmul(v[k], make_float2(wf.x, -wf.y));
    }
    fft10<+1>(v);
}
__device__ __forceinline__ void fft320_inv(float2 v[10], int lane) { fft320_inv_t<true>(v, lane); }

// ---------------- block reduction (deterministic tree) ----------------
__device__ __forceinline__ float block_reduce_256(float v) {
    __shared__ float red[256];
    red[threadIdx.x] = v;
    __syncthreads();
    #pragma unroll
    for (int s = 128; s > 0; s >>= 1) {
        if (threadIdx.x < s) red[threadIdx.x] += red[threadIdx.x + s];
        __syncthreads();
    }
    return red[0];
}

// ---------------- twiddle table init (one-time per call, exact) ----------------
__global__ void __launch_bounds__(256) k_twinit() {
    int t = blockIdx.x * 256 + threadIdx.x;
    if (t < 288) {
        int k = t / 32 + 1, l = t & 31;
        double a = -2.0 * M_PI * (double)(k * l) / 320.0;
        double s, c; sincos(a, &s, &c);
        g_tw320[t] = make_float2((float)c, (float)s);
    } else if (t < 416) {
        int u = t - 288;
        int s2 = u >> 5, l = u & 31;
        int m = 16 >> s2;
        if (l & m) {                      // up lanes: real stage twiddle
            int j = l & (m - 1);
            double a = -M_PI * (double)j / (double)m;
            double ss, cc; sincos(a, &ss, &cc);
            g_tw32[u] = make_float2((float)cc, (float)ss);
        } else {                          // down lanes: unit twiddle
            g_tw32[u] = make_float2(1.f, 0.f);
        }
    }
}

// ---------------- csm prep: fp32 -> fp16 complex, PAIRED row layout ----------------
// mem[row*320 + 2*lane + 64*t + s] = nat[row*320 + lane + 32*(2t+s)]
__global__ void __launch_bounds__(256) k_csmprep(const float* __restrict__ csm) {
    int o = blockIdx.x * 256 + threadIdx.x;   // output (paired) index, [0, B*NC*HW)
    int row = o / 320, m = o - row * 320;
    int lane = (m >> 1) & 31, s = m & 1, t = m >> 6;
    int w = lane + 32 * (2 * t + s);
    float2 c = ((const float2*)csm)[row * 320 + w];
    g_csmh[o] = __floats2half2_rn(c.x, c.y);
}

// ---------------- mask prep: (P, Q) pairs for the fused L·M·L stage ----------------
// element index e <-> (idx = lane + 32*j) in H, w_mem paired in W.
// P = m_own + m_partner ; Q = (lane even) ? m_own - m_partner : m_partner - m_own
// where partner is lane^1 (the m=1 butterfly pair), at the same j and wfreq.
__global__ void __launch_bounds__(256) k_maskprep(const int* __restrict__ mask) {
    int e = blockIdx.x * 256 + threadIdx.x;      // [0, B*HW)
    int b = e / HW; int rem = e - b * HW;
    int w_mem = rem / 320; int idx = rem - w_mem * 320;
    int l = idx & 31, j = idx >> 5;
    int hfreq_own = 10 * br5(l) + j;
    int hfreq_par = 10 * br5(l ^ 1) + j;
    int wl = (w_mem >> 1) & 31, ws = w_mem & 1, wt = w_mem >> 6;
    int wfreq = 10 * br5(wl) + 2 * wt + ws;
    int m_own = mask[b * HW + hfreq_own * 320 + wfreq];
    int m_par = mask[b * HW + hfreq_par * 320 + wfreq];
    int P = m_own + m_par;
    int Q = (l & 1) ? (m_par - m_own) : (m_own - m_par);
    g_maskPQ[e] = make_char2((char)P, (char)Q);
}

// ---------------- K1: coil = csm*p ; forward row FFT ; fp16 paired stores ----------------
__global__ void __launch_bounds__(256) k_rows_fwd() {
    int warp = threadIdx.x >> 5, lane = threadIdx.x & 31;
    int row = blockIdx.x * 8 + warp;          // bc*320 + h
    int bc = row / 320, h = row - bc * 320;
    int b = bc >> 4;
    const uint2* crow2 = (const uint2*)(g_csmh + bc * HW + h * WW);  // paired: 2 complex/load
    const float2* prow = g_p + b * HW + h * WW;
    float2 v[10];
    #pragma unroll
    for (int t = 0; t < 5; t++) {
        uint2 q = crow2[lane + 32 * t];
        float2 cv0 = unpack_c(q.x);           // natural j = 2t
        float2 cv1 = unpack_c(q.y);           // natural j = 2t+1
        v[2*t]   = cmul(cv0, prow[lane + 32 * (2*t)]);
        v[2*t+1] = cmul(cv1, prow[lane + 32 * (2*t+1)]);
    }
    fft320_fwd(v, lane);
    uint2* out2 = (uint2*)(g_k + bc * HW + h * WW);
    #pragma unroll
    for (int t = 0; t < 5; t++) {
        uint2 q;
        q.x = pack_c(v[2*t]);
        q.y = pack_c(v[2*t+1]);
        out2[lane + 32 * t] = q;
    }
}

// ---------------- K2: column FFT + fused mask stage + column IFFT ----------------
__global__ void __launch_bounds__(256) k_cols() {
    __shared__ float2 sC[8][326];     // stride 326: rows c and c+4 are 16 banks apart
    int bc = blockIdx.x / 40;
    int w0 = (blockIdx.x - bc * 40) * 8;
    int b = bc >> 4;
    __half2* base = g_k + bc * HW;

    for (int pidx = threadIdx.x; pidx < 640; pidx += 256) {
        int h = pidx >> 1, q = pidx & 1;
        uint4 t4 = ((const uint4*)(base + h * WW + w0))[q];
        int c = 4 * q;
        sC[c][h]   = unpack_c(t4.x);
        sC[c+1][h] = unpack_c(t4.y);
        sC[c+2][h] = unpack_c(t4.z);
        sC[c+3][h] = unpack_c(t4.w);
    }
    __syncthreads();

    int warp = threadIdx.x >> 5, lane = threadIdx.x & 31;
    float2 v[10];
    #pragma unroll
    for (int j = 0; j < 10; j++) v[j] = sC[warp][lane + 32 * j];

    fft320_fwd_t<false>(v, lane);     // skip final m=1 butterfly

    // fused L·M·L stage: v' = P*v + Q*shfl1(v)
    const char2* mrow = g_maskPQ + b * HW + (w0 + warp) * 320;
    #pragma unroll
    for (int j = 0; j < 10; j++) {
        char2 pq = mrow[lane + 32 * j];
        float P = (float)pq.x, Q = (float)pq.y;
        float ox = __shfl_xor_sync(0xffffffffu, v[j].x, 1);
        float oy = __shfl_xor_sync(0xffffffffu, v[j].y, 1);
        v[j] = make_float2(fmaf(Q, ox, P * v[j].x), fmaf(Q, oy, P * v[j].y));
    }

    fft320_inv_t<false>(v, lane);     // skip initial m=1 butterfly

    #pragma unroll
    for (int j = 0; j < 10; j++) sC[warp][lane + 32 * j] = v[j];
    __syncthreads();
    for (int pidx = threadIdx.x; pidx < 640; pidx += 256) {
        int h = pidx >> 1, q = pidx & 1;
        int c = 4 * q;
        uint4 t4;
        t4.x = pack_c(sC[c][h]);
        t4.y = pack_c(sC[c+1][h]);
        t4.z = pack_c(sC[c+2][h]);
        t4.w = pack_c(sC[c+3][h]);
        ((uint4*)(base + h * WW + w0))[q] = t4;
    }
}

// ---------------- K3: inverse row FFT + conj(csm) + combine + scale + lam*p ;
//                  last block per batch computes alpha ----------------
__global__ void __launch_bounds__(256) k_inv_combine(const float* __restrict__ lam) {
    __shared__ float2 sAcc[8][320];
    int warp = threadIdx.x >> 5, lane = threadIdx.x & 31;
    int b = blockIdx.x / 320, h = blockIdx.x - b * 320;

    float2 acc[10];
    #pragma unroll
    for (int j = 0; j < 10; j++) acc[j] = make_float2(0.f, 0.f);

    #pragma unroll
    for (int cc = 0; cc < 2; cc++) {
        int bc = b * 16 + warp + 8 * cc;
        const uint2* krow2 = (const uint2*)(g_k + bc * HW + h * WW);
        float2 v[10];
        #pragma unroll
        for (int t = 0; t < 5; t++) {
            uint2 q = krow2[lane + 32 * t];
            v[2*t]   = unpack_c(q.x);
            v[2*t+1] = unpack_c(q.y);
        }
        fft320_inv(v, lane);
        const uint2* crow2 = (const uint2*)(g_csmh + bc * HW + h * WW);  // paired
        #pragma unroll
        for (int t = 0; t < 5; t++) {
            uint2 q = crow2[lane + 32 * t];
            float2 cv0 = unpack_c(q.x);
            float2 cv1 = unpack_c(q.y);
            // acc += conj(cv) * v
            acc[2*t].x   += cv0.x * v[2*t].x   + cv0.y * v[2*t].y;
            acc[2*t].y   += cv0.x * v[2*t].y   - cv0.y * v[2*t].x;
            acc[2*t+1].x += cv1.x * v[2*t+1].x + cv1.y * v[2*t+1].y;
            acc[2*t+1].y += cv1.x * v[2*t+1].y - cv1.y * v[2*t+1].x;
        }
    }
    #pragma unroll
    for (int j = 0; j < 10; j++) sAcc[warp][lane + 32 * j] = acc[j];
    __syncthreads();

    const float2* prow = g_p + b * HW + h * WW;
    float2* aprow = g_Ap + b * HW + h * WW;
    float l0 = lam[0];
    float dot = 0.f;
    for (int e = threadIdx.x; e < 320; e += 256) {
        float2 s = make_float2(0.f, 0.f);
        #pragma unroll
        for (int w = 0; w < 8; w++) { s.x += sAcc[w][e].x; s.y += sAcc[w][e].y; }
        float2 pv = prow[e];
        float2 ap = make_float2(s.x * SCALE_N2 + l0 * pv.x, s.y * SCALE_N2 + l0 * pv.y);
        aprow[e] = ap;
        dot += pv.x * ap.x + pv.y * ap.y;
    }
    float tot = block_reduce_256(dot);

    __shared__ bool isLast;
    if (threadIdx.x == 0) {
        g_partPA[blockIdx.x] = tot;   // index = b*320 + h
        __threadfence();
        unsigned c = atomicAdd(&g_cntPA[b], 1u);
        isLast = (c == HH - 1);
    }
    __syncthreads();
    if (isLast) {
        float v = 0.f;
        for (int t = threadIdx.x; t < HH; t += 256) v += g_partPA[b * HH + t];
        float s = block_reduce_256(v);
        if (threadIdx.x == 0) {
            g_alpha[b] = g_rTr[b] / s;
            g_cntPA[b] = 0;           // reset for next iteration / replay
        }
    }
}

// ---------------- K4: x += a p ; r -= a Ap ; rr partial ; last block computes beta ----------------
__global__ void __launch_bounds__(256) k_update_xr() {
    int b = blockIdx.x / UPD_BLKS;
    int blk = blockIdx.x - b * UPD_BLKS;
    float a = g_alpha[b];

    int e4 = b * (HW / 2) + blk * 256 + threadIdx.x;   // float4 index (2 complex)
    const float4* p4  = (const float4*)g_p;
    const float4* ap4 = (const float4*)g_Ap;
    float4* x4 = (float4*)g_x;
    float4* r4 = (float4*)g_r;

    float4 pv = p4[e4], ap = ap4[e4];
    float4 xv = x4[e4];
    xv.x += a * pv.x; xv.y += a * pv.y; xv.z += a * pv.z; xv.w += a * pv.w;
    x4[e4] = xv;
    float4 rv = r4[e4];
    rv.x -= a * ap.x; rv.y -= a * ap.y; rv.z -= a * ap.z; rv.w -= a * ap.w;
    r4[e4] = rv;
    float rr = rv.x * rv.x + rv.y * rv.y + rv.z * rv.z + rv.w * rv.w;
    float tot = block_reduce_256(rr);

    __shared__ bool isLast;
    if (threadIdx.x == 0) {
        g_partRR[blockIdx.x] = tot;
        __threadfence();
        unsigned c = atomicAdd(&g_cntRR[b], 1u);
        isLast = (c == UPD_BLKS - 1);
    }
    __syncthreads();
    if (isLast) {
        float v = 0.f;
        for (int t = threadIdx.x; t < UPD_BLKS; t += 256) v += g_partRR[b * UPD_BLKS + t];
        float s = block_reduce_256(v);
        if (threadIdx.x == 0) {
            g_beta[b] = s / g_rTr[b];
            g_rTr[b] = s;
            g_cntRR[b] = 0;
        }
    }
}

// ---------------- K5: p = r + beta p (float4) ----------------
__global__ void __launch_bounds__(256) k_update_p() {
    int b = blockIdx.x / UPD_BLKS;
    int blk = blockIdx.x - b * UPD_BLKS;
    float be = g_beta[b];
    int e4 = b * (HW / 2) + blk * 256 + threadIdx.x;
    const float4* r4 = (const float4*)g_r;
    float4* p4 = (float4*)g_p;
    float4 rv = r4[e4], pv = p4[e4];
    p4[e4] = make_float4(rv.x + be * pv.x, rv.y + be * pv.y,
                         rv.z + be * pv.z, rv.w + be * pv.w);
}

// ---------------- init: p=r=rhs, x=0, rr partials (float4) ----------------
__global__ void __launch_bounds__(256) k_init(const float* __restrict__ rhs) {
    int b = blockIdx.x / INIT_BLKS;
    int blk = blockIdx.x - b * INIT_BLKS;
    int i4 = blk * 256 + threadIdx.x;            // [0, 25600): float4 over real plane
    const float4* re4 = (const float4*)(rhs + (2 * b) * HW);
    const float4* im4 = (const float4*)(rhs + (2 * b + 1) * HW);
    float4 re = re4[i4], im = im4[i4];
    float4 lo = make_float4(re.x, im.x, re.y, im.y);
    float4 hi = make_float4(re.z, im.z, re.w, im.w);
    float4* p4 = (float4*)(g_p + b * HW);
    float4* r4 = (float4*)(g_r + b * HW);
    float4* x4 = (float4*)(g_x + b * HW);
    p4[2*i4] = lo; p4[2*i4+1] = hi;
    r4[2*i4] = lo; r4[2*i4+1] = hi;
    x4[2*i4]   = make_float4(0.f, 0.f, 0.f, 0.f);
    x4[2*i4+1] = make_float4(0.f, 0.f, 0.f, 0.f);
    float rr = re.x*re.x + re.y*re.y + re.z*re.z + re.w*re.w
             + im.x*im.x + im.y*im.y + im.z*im.z + im.w*im.w;
    float tot = block_reduce_256(rr);
    if (threadIdx.x == 0) g_partI[blockIdx.x] = tot;
}

__global__ void __launch_bounds__(256) k_init_red() {
    int b = blockIdx.x;
    float v = 0.f;
    for (int t = threadIdx.x; t < INIT_BLKS; t += 256) v += g_partI[b * INIT_BLKS + t];
    float tot = block_reduce_256(v);
    if (threadIdx.x == 0) g_rTr[b] = tot;
}

// ---------------- output: [B,H,W,2] (float4 copy of g_x) ----------------
__global__ void __launch_bounds__(256) k_out(float* __restrict__ out) {
    int e = blockIdx.x * 256 + threadIdx.x;   // [0, 409600)
    ((float4*)out)[e] = ((const float4*)g_x)[e];
}

// ---------------- launch ----------------
extern "C" void kernel_launch(void* const* d_in, const int* in_sizes, int n_in,
                              void* d_out, int out_size) {
    const float* rhs  = (const float*)d_in[0];
    const float* csm  = (const float*)d_in[1];
    const int*   mask = (const int*)d_in[2];
    const float* lam  = (const float*)d_in[3];
    float* out = (float*)d_out;

    const int FG = BATCH * NC * HH / 8;   // 5120
    const int CG = BATCH * NC * (WW / 8); // 5120
    const int IG = BATCH * HH;            // 2560
    const int UG = BATCH * UPD_BLKS;      // 1600

    k_twinit<<<2, 256>>>();
    k_csmprep<<<BATCH * NC * HW / 256, 256>>>(csm);
    k_maskprep<<<BATCH * HW / 256, 256>>>(mask);
    k_init<<<BATCH * INIT_BLKS, 256>>>(rhs);
    k_init_red<<<BATCH, 256>>>();

    for (int it = 0; it < NITER; it++) {
        k_rows_fwd<<<FG, 256>>>();
        k_cols<<<CG, 256>>>();
        k_inv_combine<<<IG, 256>>>(lam);
        k_update_xr<<<UG, 256>>>();
        k_update_p<<<UG, 256>>>();
    }

    k_out<<<BATCH * HW / 512, 256>>>(out);
}

// round 14
// speedup vs baseline: 1.0344x; 1.0344x over previous
#include <cuda_runtime.h>
#include <cuda_fp16.h>
#include <math.h>

// Problem constants
#define BATCH 8
#define NC    16
#define HH    320
#define WW    320
#define HW    102400
#define NITER 10
#define INIT_BLKS 100   // blocks/batch in k_init
#define UPD_BLKS  200   // blocks/batch in update kernels
#define SCALE_N2 (1.0f / 102400.0f)

// ---------------- scratch (device globals; no runtime allocation) ----------------
__device__ __align__(16) __half2 g_k[BATCH * NC * HW];   // coil k-space, fp16 complex (paired permuted layout)
__device__ __align__(16) __half2 g_csmh[BATCH * NC * HW];// csm fp16 complex, PAIRED layout per row
__device__ __align__(16) float2 g_x[BATCH * HW];
__device__ __align__(16) float2 g_r[BATCH * HW];
__device__ __align__(16) float2 g_p[BATCH * HW];
__device__ __align__(16) float2 g_Ap[BATCH * HW];
__device__ __align__(16) char2 g_maskPQ[BATCH * HW];    // (P, Q) pairs for fused mask stage
__device__ float  g_partPA[BATCH * HH];                 // p.Ap partials
__device__ float  g_partRR[BATCH * UPD_BLKS];           // r.r partials
__device__ float  g_partI[BATCH * INIT_BLKS];           // init rr partials
__device__ float  g_rTr[BATCH];
__device__ float  g_alpha[BATCH];
__device__ float  g_beta[BATCH];
__device__ unsigned g_cntPA[BATCH];                     // last-block counters (self-resetting)
__device__ unsigned g_cntRR[BATCH];
__device__ float2 g_tw320[288];           // exp(-2pi i k*lane/320), k=1..9
__device__ float2 g_tw32[128];            // fft32 stage twiddles; DOWN lanes hold (1,0)

// ---------------- complex helpers ----------------
__device__ __forceinline__ float2 cmul(float2 a, float2 b) {
    return make_float2(a.x*b.x - a.y*b.y, a.x*b.y + a.y*b.x);
}
__device__ __forceinline__ float2 cadd(float2 a, float2 b) { return make_float2(a.x+b.x, a.y+b.y); }
__device__ __forceinline__ float2 csub(float2 a, float2 b) { return make_float2(a.x-b.x, a.y-b.y); }
__device__ __forceinline__ int br5(int l) { return (int)(__brev((unsigned)l) >> 27); }

__device__ __forceinline__ unsigned pack_c(float2 v) {
    __half2 h = __floats2half2_rn(v.x, v.y);
    return *(unsigned*)&h;
}
__device__ __forceinline__ float2 unpack_c(unsigned u) {
    __half2 h = *(__half2*)&u;
    return __half22float2(h);
}

// ---------------- radix-5 ----------------
#define C51 0.30901699437494745f
#define C52 (-0.8090169943749475f)
#define S51 0.9510565162951535f
#define S52 0.5877852522924731f

template<int DIR>
__device__ __forceinline__ void fft5(float2 a0, float2 a1, float2 a2, float2 a3, float2 a4,
                                     float2& b0, float2& b1, float2& b2, float2& b3, float2& b4) {
    const float dir = (float)DIR;
    float2 t1 = cadd(a1, a4), t2 = cadd(a2, a3);
    float2 t3 = csub(a1, a4), t4 = csub(a2, a3);
    float2 m1 = make_float2(a0.x + C51*t1.x + C52*t2.x, a0.y + C51*t1.y + C52*t2.y);
    float2 m2 = make_float2(a0.x + C52*t1.x + C51*t2.x, a0.y + C52*t1.y + C51*t2.y);
    float2 u1 = make_float2(S51*t3.x + S52*t4.x, S51*t3.y + S52*t4.y);
    float2 u2 = make_float2(S52*t3.x - S51*t4.x, S52*t3.y - S51*t4.y);
    b0 = make_float2(a0.x + t1.x + t2.x, a0.y + t1.y + t2.y);
    b1 = make_float2(m1.x - dir*u1.y, m1.y + dir*u1.x);
    b4 = make_float2(m1.x + dir*u1.y, m1.y - dir*u1.x);
    b2 = make_float2(m2.x - dir*u2.y, m2.y + dir*u2.x);
    b3 = make_float2(m2.x + dir*u2.y, m2.y - dir*u2.x);
}

// ---------------- per-lane 10-point FFT ----------------
template<int DIR>
__device__ __forceinline__ void fft10(float2 v[10]) {
    const float dir = (float)DIR;
    float2 e0,e1,e2,e3,e4, o0,o1,o2,o3,o4;
    fft5<DIR>(v[0], v[2], v[4], v[6], v[8], e0, e1, e2, e3, e4);
    fft5<DIR>(v[1], v[3], v[5], v[7], v[9], o0, o1, o2, o3, o4);
    const float c1 = 0.80901699437494745f, s1 = 0.58778525229247314f;
    const float c2 = 0.30901699437494745f, s2 = 0.95105651629515357f;
    float2 t;
    v[0] = cadd(e0, o0);                       v[5] = csub(e0, o0);
    t = cmul(o1, make_float2( c1, dir*s1));    v[1] = cadd(e1, t); v[6] = csub(e1, t);
    t = cmul(o2, make_float2( c2, dir*s2));    v[2] = cadd(e2, t); v[7] = csub(e2, t);
    t = cmul(o3, make_float2(-c2, dir*s2));    v[3] = cadd(e3, t); v[8] = csub(e3, t);
    t = cmul(o4, make_float2(-c1, dir*s1));    v[4] = cadd(e4, t); v[9] = csub(e4, t);
}

// ---------------- full 320-pt forward; LAST=false skips final m=1 butterfly ----------------
// v[j]=x[lane+32j] -> lane holds X[10*br5(lane)+j] (when LAST=true)
template<bool LAST>
__device__ __forceinline__ void fft320_fwd_t(float2 v[10], int lane) {
    fft10<-1>(v);
    #pragma unroll
    for (int k = 1; k < 10; k++) v[k] = cmul(v[k], g_tw320[(k-1)*32 + lane]);
    #pragma unroll
    for (int s = 0; s < 4; s++) {
        int m = 16 >> s;
        float2 w = g_tw32[s*32 + lane];           // (1,0) on down lanes
        float sg = (lane & m) ? -1.f : 1.f;
        #pragma unroll
        for (int r = 0; r < 10; r++) {
            float ox = __shfl_xor_sync(0xffffffffu, v[r].x, m);
            float oy = __shfl_xor_sync(0xffffffffu, v[r].y, m);
            float tx = fmaf(sg, v[r].x, ox);
            float ty = fmaf(sg, v[r].y, oy);
            v[r] = cmul(make_float2(tx, ty), w);
        }
    }
    if (LAST) {
        float sg1 = (lane & 1) ? -1.f : 1.f;      // m=1: no twiddle
        #pragma unroll
        for (int r = 0; r < 10; r++) {
            float ox = __shfl_xor_sync(0xffffffffu, v[r].x, 1);
            float oy = __shfl_xor_sync(0xffffffffu, v[r].y, 1);
            v[r] = make_float2(fmaf(sg1, v[r].x, ox), fmaf(sg1, v[r].y, oy));
        }
    }
}
__device__ __forceinline__ void fft320_fwd(float2 v[10], int lane) { fft320_fwd_t<true>(v, lane); }

// ---------------- full 320-pt inverse (unnormalized); FIRST=false skips initial m=1 butterfly ----------------
template<bool FIRST>
__device__ __forceinline__ void fft320_inv_t(float2 v[10], int lane) {
    if (FIRST) {
        float sg1 = (lane & 1) ? -1.f : 1.f;      // m=1: no twiddle
        #pragma unroll
        for (int r = 0; r < 10; r++) {
            float ox = __shfl_xor_sync(0xffffffffu, v[r].x, 1);
            float oy = __shfl_xor_sync(0xffffffffu, v[r].y, 1);
            v[r] = make_float2(fmaf(sg1, v[r].x, ox), fmaf(sg1, v[r].y, oy));
        }
    }
    #pragma unroll
    for (int s = 3; s >= 0; s--) {
        int m = 16 >> s;
        float2 wf = g_tw32[s*32 + lane];
        float2 w = make_float2(wf.x, -wf.y);      // conj
        float sg = (lane & m) ? -1.f : 1.f;
        #pragma unroll
        for (int r = 0; r < 10; r++) {
            float2 u = cmul(v[r], w);             // pre-twiddle (unit on down lanes)
            float ox = __shfl_xor_sync(0xffffffffu, u.x, m);
            float oy = __shfl_xor_sync(0xffffffffu, u.y, m);
            v[r] = make_float2(fmaf(sg, u.x, ox), fmaf(sg, u.y, oy));
        }
    }
    #pragma unroll
    for (int k = 1; k < 10; k++) {
        float2 wf = g_tw320[(k-1)*32 + lane];
        v[k] = cmul(v[k], make_float2(wf.x, -wf.y));
    }
    fft10<+1>(v);
}
__device__ __forceinline__ void fft320_inv(float2 v[10], int lane) { fft320_inv_t<true>(v, lane); }

// ---------------- block reduction (deterministic tree) ----------------
__device__ __forceinline__ float block_reduce_256(float v) {
    __shared__ float red[256];
    red[threadIdx.x] = v;
    __syncthreads();
    #pragma unroll
    for (int s = 128; s > 0; s >>= 1) {
        if (threadIdx.x < s) red[threadIdx.x] += red[threadIdx.x + s];
        __syncthreads();
    }
    return red[0];
}

// ---------------- twiddle table init (one-time per call, exact) ----------------
__global__ void __launch_bounds__(256) k_twinit() {
    int t = blockIdx.x * 256 + threadIdx.x;
    if (t < 288) {
        int k = t / 32 + 1, l = t & 31;
        double a = -2.0 * M_PI * (double)(k * l) / 320.0;
        double s, c; sincos(a, &s, &c);
        g_tw320[t] = make_float2((float)c, (float)s);
    } else if (t < 416) {
        int u = t - 288;
        int s2 = u >> 5, l = u & 31;
        int m = 16 >> s2;
        if (l & m) {                      // up lanes: real stage twiddle
            int j = l & (m - 1);
            double a = -M_PI * (double)j / (double)m;
            double ss, cc; sincos(a, &ss, &cc);
            g_tw32[u] = make_float2((float)cc, (float)ss);
        } else {                          // down lanes: unit twiddle
            g_tw32[u] = make_float2(1.f, 0.f);
        }
    }
}

// ---------------- csm prep: fp32 -> fp16 complex, PAIRED row layout ----------------
// mem[row*320 + 2*lane + 64*t + s] = nat[row*320 + lane + 32*(2t+s)]
__global__ void __launch_bounds__(256) k_csmprep(const float* __restrict__ csm) {
    int o = blockIdx.x * 256 + threadIdx.x;   // output (paired) index, [0, B*NC*HW)
    int row = o / 320, m = o - row * 320;
    int lane = (m >> 1) & 31, s = m & 1, t = m >> 6;
    int w = lane + 32 * (2 * t + s);
    float2 c = ((const float2*)csm)[row * 320 + w];
    g_csmh[o] = __floats2half2_rn(c.x, c.y);
}

// ---------------- mask prep: (P, Q) pairs for the fused L·M·L stage ----------------
// P = m_own + m_partner ; Q = (lane even) ? m_own - m_partner : m_partner - m_own
// where partner is lane^1 (the m=1 butterfly pair), at the same j and wfreq.
__global__ void __launch_bounds__(256) k_maskprep(const int* __restrict__ mask) {
    int e = blockIdx.x * 256 + threadIdx.x;      // [0, B*HW)
    int b = e / HW; int rem = e - b * HW;
    int w_mem = rem / 320; int idx = rem - w_mem * 320;
    int l = idx & 31, j = idx >> 5;
    int hfreq_own = 10 * br5(l) + j;
    int hfreq_par = 10 * br5(l ^ 1) + j;
    int wl = (w_mem >> 1) & 31, ws = w_mem & 1, wt = w_mem >> 6;
    int wfreq = 10 * br5(wl) + 2 * wt + ws;
    int m_own = mask[b * HW + hfreq_own * 320 + wfreq];
    int m_par = mask[b * HW + hfreq_par * 320 + wfreq];
    int P = m_own + m_par;
    int Q = (l & 1) ? (m_par - m_own) : (m_own - m_par);
    g_maskPQ[e] = make_char2((char)P, (char)Q);
}

// ---------------- K1: coil = csm*p ; forward row FFT ; fp16 paired stores ----------------
__global__ void __launch_bounds__(256) k_rows_fwd() {
    int warp = threadIdx.x >> 5, lane = threadIdx.x & 31;
    int row = blockIdx.x * 8 + warp;          // bc*320 + h
    int bc = row / 320, h = row - bc * 320;
    int b = bc >> 4;
    const uint2* crow2 = (const uint2*)(g_csmh + bc * HW + h * WW);  // paired: 2 complex/load
    const float2* prow = g_p + b * HW + h * WW;
    float2 v[10];
    #pragma unroll
    for (int t = 0; t < 5; t++) {
        uint2 q = crow2[lane + 32 * t];
        float2 cv0 = unpack_c(q.x);           // natural j = 2t
        float2 cv1 = unpack_c(q.y);           // natural j = 2t+1
        v[2*t]   = cmul(cv0, prow[lane + 32 * (2*t)]);
        v[2*t+1] = cmul(cv1, prow[lane + 32 * (2*t+1)]);
    }
    fft320_fwd(v, lane);
    uint2* out2 = (uint2*)(g_k + bc * HW + h * WW);
    #pragma unroll
    for (int t = 0; t < 5; t++) {
        uint2 q;
        q.x = pack_c(v[2*t]);
        q.y = pack_c(v[2*t+1]);
        out2[lane + 32 * t] = q;
    }
}

// ---------------- K2: column FFT + fused mask stage + column IFFT (split fp32 SMEM staging) ----------------
__global__ void __launch_bounds__(256) k_cols() {
    __shared__ float sRe[8][324];
    __shared__ float sIm[8][324];
    int bc = blockIdx.x / 40;
    int w0 = (blockIdx.x - bc * 40) * 8;
    int b = bc >> 4;
    __half2* base = g_k + bc * HW;

    for (int pidx = threadIdx.x; pidx < 640; pidx += 256) {
        int h = pidx >> 1, q = pidx & 1;
        uint4 t4 = ((const uint4*)(base + h * WW + w0))[q];
        int c = 4 * q;
        float2 f0 = unpack_c(t4.x), f1 = unpack_c(t4.y);
        float2 f2 = unpack_c(t4.z), f3 = unpack_c(t4.w);
        sRe[c][h]   = f0.x; sIm[c][h]   = f0.y;
        sRe[c+1][h] = f1.x; sIm[c+1][h] = f1.y;
        sRe[c+2][h] = f2.x; sIm[c+2][h] = f2.y;
        sRe[c+3][h] = f3.x; sIm[c+3][h] = f3.y;
    }
    __syncthreads();

    int warp = threadIdx.x >> 5, lane = threadIdx.x & 31;
    float2 v[10];
    #pragma unroll
    for (int j = 0; j < 10; j++) {
        int h = lane + 32 * j;
        v[j] = make_float2(sRe[warp][h], sIm[warp][h]);
    }

    fft320_fwd_t<false>(v, lane);     // skip final m=1 butterfly

    // fused L·M·L stage: v' = P*v + Q*shfl1(v)
    const char2* mrow = g_maskPQ + b * HW + (w0 + warp) * 320;
    #pragma unroll
    for (int j = 0; j < 10; j++) {
        char2 pq = mrow[lane + 32 * j];
        float P = (float)pq.x, Q = (float)pq.y;
        float ox = __shfl_xor_sync(0xffffffffu, v[j].x, 1);
        float oy = __shfl_xor_sync(0xffffffffu, v[j].y, 1);
        v[j] = make_float2(fmaf(Q, ox, P * v[j].x), fmaf(Q, oy, P * v[j].y));
    }

    fft320_inv_t<false>(v, lane);     // skip initial m=1 butterfly

    #pragma unroll
    for (int j = 0; j < 10; j++) {
        int h = lane + 32 * j;
        sRe[warp][h] = v[j].x; sIm[warp][h] = v[j].y;
    }
    __syncthreads();
    for (int pidx = threadIdx.x; pidx < 640; pidx += 256) {
        int h = pidx >> 1, q = pidx & 1;
        int c = 4 * q;
        uint4 t4;
        t4.x = pack_c(make_float2(sRe[c][h],   sIm[c][h]));
        t4.y = pack_c(make_float2(sRe[c+1][h], sIm[c+1][h]));
        t4.z = pack_c(make_float2(sRe[c+2][h], sIm[c+2][h]));
        t4.w = pack_c(make_float2(sRe[c+3][h], sIm[c+3][h]));
        ((uint4*)(base + h * WW + w0))[q] = t4;
    }
}

// ---------------- K3: inverse row FFT + conj(csm) + combine + scale + lam*p ;
//                  last block per batch computes alpha ----------------
__global__ void __launch_bounds__(256) k_inv_combine(const float* __restrict__ lam) {
    __shared__ float2 sAcc[8][320];
    int warp = threadIdx.x >> 5, lane = threadIdx.x & 31;
    int b = blockIdx.x / 320, h = blockIdx.x - b * 320;

    float2 acc[10];
    #pragma unroll
    for (int j = 0; j < 10; j++) acc[j] = make_float2(0.f, 0.f);

    #pragma unroll
    for (int cc = 0; cc < 2; cc++) {
        int bc = b * 16 + warp + 8 * cc;
        const uint2* krow2 = (const uint2*)(g_k + bc * HW + h * WW);
        float2 v[10];
        #pragma unroll
        for (int t = 0; t < 5; t++) {
            uint2 q = krow2[lane + 32 * t];
            v[2*t]   = unpack_c(q.x);
            v[2*t+1] = unpack_c(q.y);
        }
        fft320_inv(v, lane);
        const uint2* crow2 = (const uint2*)(g_csmh + bc * HW + h * WW);  // paired
        #pragma unroll
        for (int t = 0; t < 5; t++) {
            uint2 q = crow2[lane + 32 * t];
            float2 cv0 = unpack_c(q.x);
            float2 cv1 = unpack_c(q.y);
            // acc += conj(cv) * v
            acc[2*t].x   += cv0.x * v[2*t].x   + cv0.y * v[2*t].y;
            acc[2*t].y   += cv0.x * v[2*t].y   - cv0.y * v[2*t].x;
            acc[2*t+1].x += cv1.x * v[2*t+1].x + cv1.y * v[2*t+1].y;
            acc[2*t+1].y += cv1.x * v[2*t+1].y - cv1.y * v[2*t+1].x;
        }
    }
    #pragma unroll
    for (int j = 0; j < 10; j++) sAcc[warp][lane + 32 * j] = acc[j];
    __syncthreads();

    const float2* prow = g_p + b * HW + h * WW;
    float2* aprow = g_Ap + b * HW + h * WW;
    float l0 = lam[0];
    float dot = 0.f;
    for (int e = threadIdx.x; e < 320; e += 256) {
        float2 s = make_float2(0.f, 0.f);
        #pragma unroll
        for (int w = 0; w < 8; w++) { s.x += sAcc[w][e].x; s.y += sAcc[w][e].y; }
        float2 pv = prow[e];
        float2 ap = make_float2(s.x * SCALE_N2 + l0 * pv.x, s.y * SCALE_N2 + l0 * pv.y);
        aprow[e] = ap;
        dot += pv.x * ap.x + pv.y * ap.y;
    }
    float tot = block_reduce_256(dot);

    __shared__ bool isLast;
    if (threadIdx.x == 0) {
        g_partPA[blockIdx.x] = tot;   // index = b*320 + h
        __threadfence();
        unsigned c = atomicAdd(&g_cntPA[b], 1u);
        isLast = (c == HH - 1);
    }
    __syncthreads();
    if (isLast) {
        float v = 0.f;
        for (int t = threadIdx.x; t < HH; t += 256) v += g_partPA[b * HH + t];
        float s = block_reduce_256(v);
        if (threadIdx.x == 0) {
            g_alpha[b] = g_rTr[b] / s;
            g_cntPA[b] = 0;           // reset for next iteration / replay
        }
    }
}

// ---------------- K4: x += a p ; r -= a Ap ; rr partial ; last block computes beta ----------------
__global__ void __launch_bounds__(256) k_update_xr() {
    int b = blockIdx.x / UPD_BLKS;
    int blk = blockIdx.x - b * UPD_BLKS;
    float a = g_alpha[b];

    int e4 = b * (HW / 2) + blk * 256 + threadIdx.x;   // float4 index (2 complex)
    const float4* p4  = (const float4*)g_p;
    const float4* ap4 = (const float4*)g_Ap;
    float4* x4 = (float4*)g_x;
    float4* r4 = (float4*)g_r;

    float4 pv = p4[e4], ap = ap4[e4];
    float4 xv = x4[e4];
    xv.x += a * pv.x; xv.y += a * pv.y; xv.z += a * pv.z; xv.w += a * pv.w;
    x4[e4] = xv;
    float4 rv = r4[e4];
    rv.x -= a * ap.x; rv.y -= a * ap.y; rv.z -= a * ap.z; rv.w -= a * ap.w;
    r4[e4] = rv;
    float rr = rv.x * rv.x + rv.y * rv.y + rv.z * rv.z + rv.w * rv.w;
    float tot = block_reduce_256(rr);

    __shared__ bool isLast;
    if (threadIdx.x == 0) {
        g_partRR[blockIdx.x] = tot;
        __threadfence();
        unsigned c = atomicAdd(&g_cntRR[b], 1u);
        isLast = (c == UPD_BLKS - 1);
    }
    __syncthreads();
    if (isLast) {
        float v = 0.f;
        for (int t = threadIdx.x; t < UPD_BLKS; t += 256) v += g_partRR[b * UPD_BLKS + t];
        float s = block_reduce_256(v);
        if (threadIdx.x == 0) {
            g_beta[b] = s / g_rTr[b];
            g_rTr[b] = s;
            g_cntRR[b] = 0;
        }
    }
}

// ---------------- K5: p = r + beta p (float4) ----------------
__global__ void __launch_bounds__(256) k_update_p() {
    int b = blockIdx.x / UPD_BLKS;
    int blk = blockIdx.x - b * UPD_BLKS;
    float be = g_beta[b];
    int e4 = b * (HW / 2) + blk * 256 + threadIdx.x;
    const float4* r4 = (const float4*)g_r;
    float4* p4 = (float4*)g_p;
    float4 rv = r4[e4], pv = p4[e4];
    p4[e4] = make_float4(rv.x + be * pv.x, rv.y + be * pv.y,
                         rv.z + be * pv.z, rv.w + be * pv.w);
}

// ---------------- init: p=r=rhs, x=0, rr partials (float4) ----------------
__global__ void __launch_bounds__(256) k_init(const float* __restrict__ rhs) {
    int b = blockIdx.x / INIT_BLKS;
    int blk = blockIdx.x - b * INIT_BLKS;
    int i4 = blk * 256 + threadIdx.x;            // [0, 25600): float4 over real plane
    const float4* re4 = (const float4*)(rhs + (2 * b) * HW);
    const float4* im4 = (const float4*)(rhs + (2 * b + 1) * HW);
    float4 re = re4[i4], im = im4[i4];
    float4 lo = make_float4(re.x, im.x, re.y, im.y);
    float4 hi = make_float4(re.z, im.z, re.w, im.w);
    float4* p4 = (float4*)(g_p + b * HW);
    float4* r4 = (float4*)(g_r + b * HW);
    float4* x4 = (float4*)(g_x + b * HW);
    p4[2*i4] = lo; p4[2*i4+1] = hi;
    r4[2*i4] = lo; r4[2*i4+1] = hi;
    x4[2*i4]   = make_float4(0.f, 0.f, 0.f, 0.f);
    x4[2*i4+1] = make_float4(0.f, 0.f, 0.f, 0.f);
    float rr = re.x*re.x + re.y*re.y + re.z*re.z + re.w*re.w
             + im.x*im.x + im.y*im.y + im.z*im.z + im.w*im.w;
    float tot = block_reduce_256(rr);
    if (threadIdx.x == 0) g_partI[blockIdx.x] = tot;
}

__global__ void __launch_bounds__(256) k_init_red() {
    int b = blockIdx.x;
    float v = 0.f;
    for (int t = threadIdx.x; t < INIT_BLKS; t += 256) v += g_partI[b * INIT_BLKS + t];
    float tot = block_reduce_256(v);
    if (threadIdx.x == 0) g_rTr[b] = tot;
}

// ---------------- output: [B,H,W,2] (float4 copy of g_x) ----------------
__global__ void __launch_bounds__(256) k_out(float* __restrict__ out) {
    int e = blockIdx.x * 256 + threadIdx.x;   // [0, 409600)
    ((float4*)out)[e] = ((const float4*)g_x)[e];
}

// ---------------- launch ----------------
extern "C" void kernel_launch(void* const* d_in, const int* in_sizes, int n_in,
                              void* d_out, int out_size) {
    const float* rhs  = (const float*)d_in[0];
    const float* csm  = (const float*)d_in[1];
    const int*   mask = (const int*)d_in[2];
    const float* lam  = (const float*)d_in[3];
    float* out = (float*)d_out;

    const int FG = BATCH * NC * HH / 8;   // 5120
    const int CG = BATCH * NC * (WW / 8); // 5120
    const int IG = BATCH * HH;            // 2560
    const int UG = BATCH * UPD_BLKS;      // 1600

    k_twinit<<<2, 256>>>();
    k_csmprep<<<BATCH * NC * HW / 256, 256>>>(csm);
    k_maskprep<<<BATCH * HW / 256, 256>>>(mask);
    k_init<<<BATCH * INIT_BLKS, 256>>>(rhs);
    k_init_red<<<BATCH, 256>>>();

    for (int it = 0; it < NITER; it++) {
        k_rows_fwd<<<FG, 256>>>();
        k_cols<<<CG, 256>>>();
        k_inv_combine<<<IG, 256>>>(lam);
        k_update_xr<<<UG, 256>>>();
        k_update_p<<<UG, 256>>>();
    }

    k_out<<<BATCH * HW / 512, 256>>>(out);
}

// round 15
// speedup vs baseline: 1.0398x; 1.0052x over previous
#include <cuda_runtime.h>
#include <cuda_fp16.h>
#include <math.h>

// Problem constants
#define BATCH 8
#define NC    16
#define HH    320
#define WW    320
#define HW    102400
#define NITER 10
#define INIT_BLKS 100   // blocks/batch in k_init
#define UPD_BLKS  200   // blocks/batch in update kernels
#define SCALE_N2 (1.0f / 102400.0f)

// ---------------- scratch (device globals; no runtime allocation) ----------------
__device__ __align__(16) __half2 g_k[BATCH * NC * HW];   // coil k-space, fp16 complex (paired permuted layout)
__device__ __align__(16) __half2 g_csmh[BATCH * NC * HW];// csm fp16 complex, PAIRED layout per row
__device__ __align__(16) float2 g_x[BATCH * HW];
__device__ __align__(16) float2 g_r[BATCH * HW];
__device__ __align__(16) float2 g_p[BATCH * HW];
__device__ __align__(16) float2 g_Ap[BATCH * HW];
__device__ __align__(16) char2 g_maskPQ[BATCH * HW];    // (P, Q) pairs for fused mask stage
__device__ float  g_partPA[BATCH * HH];                 // p.Ap partials
__device__ float  g_partRR[BATCH * UPD_BLKS];           // r.r partials
__device__ float  g_partI[BATCH * INIT_BLKS];           // init rr partials
__device__ float  g_rTr[BATCH];
__device__ float  g_alpha[BATCH];
__device__ float  g_beta[BATCH];
__device__ unsigned g_cntPA[BATCH];                     // last-block counters (self-resetting)
__device__ unsigned g_cntRR[BATCH];
__device__ float2 g_tw320[288];           // exp(-2pi i k*lane/320), k=1..9
__device__ float2 g_tw32[128];            // fft32 stage twiddles; DOWN lanes hold (1,0)

// ---------------- complex helpers ----------------
__device__ __forceinline__ float2 cmul(float2 a, float2 b) {
    return make_float2(a.x*b.x - a.y*b.y, a.x*b.y + a.y*b.x);
}
__device__ __forceinline__ float2 cadd(float2 a, float2 b) { return make_float2(a.x+b.x, a.y+b.y); }
__device__ __forceinline__ float2 csub(float2 a, float2 b) { return make_float2(a.x-b.x, a.y-b.y); }
__device__ __forceinline__ int br5(int l) { return (int)(__brev((unsigned)l) >> 27); }

__device__ __forceinline__ unsigned pack_c(float2 v) {
    __half2 h = __floats2half2_rn(v.x, v.y);
    return *(unsigned*)&h;
}
__device__ __forceinline__ float2 unpack_c(unsigned u) {
    __half2 h = *(__half2*)&u;
    return __half22float2(h);
}

// ---------------- radix-5 ----------------
#define C51 0.30901699437494745f
#define C52 (-0.8090169943749475f)
#define S51 0.9510565162951535f
#define S52 0.5877852522924731f

template<int DIR>
__device__ __forceinline__ void fft5(float2 a0, float2 a1, float2 a2, float2 a3, float2 a4,
                                     float2& b0, float2& b1, float2& b2, float2& b3, float2& b4) {
    const float dir = (float)DIR;
    float2 t1 = cadd(a1, a4), t2 = cadd(a2, a3);
    float2 t3 = csub(a1, a4), t4 = csub(a2, a3);
    float2 m1 = make_float2(a0.x + C51*t1.x + C52*t2.x, a0.y + C51*t1.y + C52*t2.y);
    float2 m2 = make_float2(a0.x + C52*t1.x + C51*t2.x, a0.y + C52*t1.y + C51*t2.y);
    float2 u1 = make_float2(S51*t3.x + S52*t4.x, S51*t3.y + S52*t4.y);
    float2 u2 = make_float2(S52*t3.x - S51*t4.x, S52*t3.y - S51*t4.y);
    b0 = make_float2(a0.x + t1.x + t2.x, a0.y + t1.y + t2.y);
    b1 = make_float2(m1.x - dir*u1.y, m1.y + dir*u1.x);
    b4 = make_float2(m1.x + dir*u1.y, m1.y - dir*u1.x);
    b2 = make_float2(m2.x - dir*u2.y, m2.y + dir*u2.x);
    b3 = make_float2(m2.x + dir*u2.y, m2.y - dir*u2.x);
}

// ---------------- per-lane 10-point FFT ----------------
template<int DIR>
__device__ __forceinline__ void fft10(float2 v[10]) {
    const float dir = (float)DIR;
    float2 e0,e1,e2,e3,e4, o0,o1,o2,o3,o4;
    fft5<DIR>(v[0], v[2], v[4], v[6], v[8], e0, e1, e2, e3, e4);
    fft5<DIR>(v[1], v[3], v[5], v[7], v[9], o0, o1, o2, o3, o4);
    const float c1 = 0.80901699437494745f, s1 = 0.58778525229247314f;
    const float c2 = 0.30901699437494745f, s2 = 0.95105651629515357f;
    float2 t;
    v[0] = cadd(e0, o0);                       v[5] = csub(e0, o0);
    t = cmul(o1, make_float2( c1, dir*s1));    v[1] = cadd(e1, t); v[6] = csub(e1, t);
    t = cmul(o2, make_float2( c2, dir*s2));    v[2] = cadd(e2, t); v[7] = csub(e2, t);
    t = cmul(o3, make_float2(-c2, dir*s2));    v[3] = cadd(e3, t); v[8] = csub(e3, t);
    t = cmul(o4, make_float2(-c1, dir*s1));    v[4] = cadd(e4, t); v[9] = csub(e4, t);
}

// ---------------- full 320-pt forward; LAST=false skips final m=1 butterfly ----------------
// v[j]=x[lane+32j] -> lane holds X[10*br5(lane)+j] (when LAST=true)
template<bool LAST>
__device__ __forceinline__ void fft320_fwd_t(float2 v[10], int lane) {
    fft10<-1>(v);
    #pragma unroll
    for (int k = 1; k < 10; k++) v[k] = cmul(v[k], g_tw320[(k-1)*32 + lane]);
    #pragma unroll
    for (int s = 0; s < 4; s++) {
        int m = 16 >> s;
        float2 w = g_tw32[s*32 + lane];           // (1,0) on down lanes
        float sg = (lane & m) ? -1.f : 1.f;
        #pragma unroll
        for (int r = 0; r < 10; r++) {
            float ox = __shfl_xor_sync(0xffffffffu, v[r].x, m);
            float oy = __shfl_xor_sync(0xffffffffu, v[r].y, m);
            float tx = fmaf(sg, v[r].x, ox);
            float ty = fmaf(sg, v[r].y, oy);
            v[r] = cmul(make_float2(tx, ty), w);
        }
    }
    if (LAST) {
        float sg1 = (lane & 1) ? -1.f : 1.f;      // m=1: no twiddle
        #pragma unroll
        for (int r = 0; r < 10; r++) {
            float ox = __shfl_xor_sync(0xffffffffu, v[r].x, 1);
            float oy = __shfl_xor_sync(0xffffffffu, v[r].y, 1);
            v[r] = make_float2(fmaf(sg1, v[r].x, ox), fmaf(sg1, v[r].y, oy));
        }
    }
}
__device__ __forceinline__ void fft320_fwd(float2 v[10], int lane) { fft320_fwd_t<true>(v, lane); }

// ---------------- full 320-pt inverse (unnormalized); FIRST=false skips initial m=1 butterfly ----------------
template<bool FIRST>
__device__ __forceinline__ void fft320_inv_t(float2 v[10], int lane) {
    if (FIRST) {
        float sg1 = (lane & 1) ? -1.f : 1.f;      // m=1: no twiddle
        #pragma unroll
        for (int r = 0; r < 10; r++) {
            float ox = __shfl_xor_sync(0xffffffffu, v[r].x, 1);
            float oy = __shfl_xor_sync(0xffffffffu, v[r].y, 1);
            v[r] = make_float2(fmaf(sg1, v[r].x, ox), fmaf(sg1, v[r].y, oy));
        }
    }
    #pragma unroll
    for (int s = 3; s >= 0; s--) {
        int m = 16 >> s;
        float2 wf = g_tw32[s*32 + lane];
        float2 w = make_float2(wf.x, -wf.y);      // conj
        float sg = (lane & m) ? -1.f : 1.f;
        #pragma unroll
        for (int r = 0; r < 10; r++) {
            float2 u = cmul(v[r], w);             // pre-twiddle (unit on down lanes)
            float ox = __shfl_xor_sync(0xffffffffu, u.x, m);
            float oy = __shfl_xor_sync(0xffffffffu, u.y, m);
            v[r] = make_float2(fmaf(sg, u.x, ox), fmaf(sg, u.y, oy));
        }
    }
    #pragma unroll
    for (int k = 1; k < 10; k++) {
        float2 wf = g_tw320[(k-1)*32 + lane];
        v[k] = cmul(v[k], make_float2(wf.x, -wf.y));
    }
    fft10<+1>(v);
}
__device__ __forceinline__ void fft320_inv(float2 v[10], int lane) { fft320_inv_t<true>(v, lane); }

// ---------------- block reduction (deterministic tree) ----------------
__device__ __forceinline__ float block_reduce_256(float v) {
    __shared__ float red[256];
    red[threadIdx.x] = v;
    __syncthreads();
    #pragma unroll
    for (int s = 128; s > 0; s >>= 1) {
        if (threadIdx.x < s) red[threadIdx.x] += red[threadIdx.x + s];
        __syncthreads();
    }
    return red[0];
}

// ---------------- twiddle table init (one-time per call, exact) ----------------
__global__ void __launch_bounds__(256) k_twinit() {
    int t = blockIdx.x * 256 + threadIdx.x;
    if (t < 288) {
        int k = t / 32 + 1, l = t & 31;
        double a = -2.0 * M_PI * (double)(k * l) / 320.0;
        double s, c; sincos(a, &s, &c);
        g_tw320[t] = make_float2((float)c, (float)s);
    } else if (t < 416) {
        int u = t - 288;
        int s2 = u >> 5, l = u & 31;
        int m = 16 >> s2;
        if (l & m) {                      // up lanes: real stage twiddle
            int j = l & (m - 1);
            double a = -M_PI * (double)j / (double)m;
            double ss, cc; sincos(a, &ss, &cc);
            g_tw32[u] = make_float2((float)cc, (float)ss);
        } else {                          // down lanes: unit twiddle
            g_tw32[u] = make_float2(1.f, 0.f);
        }
    }
}

// ---------------- csm prep: fp32 -> fp16 complex, PAIRED row layout ----------------
// mem[row*320 + 2*lane + 64*t + s] = nat[row*320 + lane + 32*(2t+s)]
__global__ void __launch_bounds__(256) k_csmprep(const float* __restrict__ csm) {
    int o = blockIdx.x * 256 + threadIdx.x;   // output (paired) index, [0, B*NC*HW)
    int row = o / 320, m = o - row * 320;
    int lane = (m >> 1) & 31, s = m & 1, t = m >> 6;
    int w = lane + 32 * (2 * t + s);
    float2 c = ((const float2*)csm)[row * 320 + w];
    g_csmh[o] = __floats2half2_rn(c.x, c.y);
}

// ---------------- mask prep: (P, Q) pairs for the fused L·M·L stage ----------------
// P = m_own + m_partner ; Q = (lane even) ? m_own - m_partner : m_partner - m_own
// where partner is lane^1 (the m=1 butterfly pair), at the same j and wfreq.
__global__ void __launch_bounds__(256) k_maskprep(const int* __restrict__ mask) {
    int e = blockIdx.x * 256 + threadIdx.x;      // [0, B*HW)
    int b = e / HW; int rem = e - b * HW;
    int w_mem = rem / 320; int idx = rem - w_mem * 320;
    int l = idx & 31, j = idx >> 5;
    int hfreq_own = 10 * br5(l) + j;
    int hfreq_par = 10 * br5(l ^ 1) + j;
    int wl = (w_mem >> 1) & 31, ws = w_mem & 1, wt = w_mem >> 6;
    int wfreq = 10 * br5(wl) + 2 * wt + ws;
    int m_own = mask[b * HW + hfreq_own * 320 + wfreq];
    int m_par = mask[b * HW + hfreq_par * 320 + wfreq];
    int P = m_own + m_par;
    int Q = (l & 1) ? (m_par - m_own) : (m_own - m_par);
    g_maskPQ[e] = make_char2((char)P, (char)Q);
}

// ---------------- K1: coil = csm*p ; forward row FFT ; fp16 paired stores ----------------
__global__ void __launch_bounds__(256) k_rows_fwd() {
    int warp = threadIdx.x >> 5, lane = threadIdx.x & 31;
    int row = blockIdx.x * 8 + warp;          // bc*320 + h
    int bc = row / 320, h = row - bc * 320;
    int b = bc >> 4;
    const uint2* crow2 = (const uint2*)(g_csmh + bc * HW + h * WW);  // paired: 2 complex/load
    const float2* prow = g_p + b * HW + h * WW;
    float2 v[10];
    #pragma unroll
    for (int t = 0; t < 5; t++) {
        uint2 q = crow2[lane + 32 * t];
        float2 cv0 = unpack_c(q.x);           // natural j = 2t
        float2 cv1 = unpack_c(q.y);           // natural j = 2t+1
        v[2*t]   = cmul(cv0, prow[lane + 32 * (2*t)]);
        v[2*t+1] = cmul(cv1, prow[lane + 32 * (2*t+1)]);
    }
    fft320_fwd(v, lane);
    uint2* out2 = (uint2*)(g_k + bc * HW + h * WW);
    #pragma unroll
    for (int t = 0; t < 5; t++) {
        uint2 q;
        q.x = pack_c(v[2*t]);
        q.y = pack_c(v[2*t+1]);
        out2[lane + 32 * t] = q;
    }
}

// ---------------- K2: column FFT + fused mask stage + column IFFT (split fp32 SMEM staging) ----------------
__global__ void __launch_bounds__(256) k_cols() {
    __shared__ float sRe[8][324];
    __shared__ float sIm[8][324];
    int bc = blockIdx.x / 40;
    int w0 = (blockIdx.x - bc * 40) * 8;
    int b = bc >> 4;
    __half2* base = g_k + bc * HW;

    for (int pidx = threadIdx.x; pidx < 640; pidx += 256) {
        int h = pidx >> 1, q = pidx & 1;
        uint4 t4 = ((const uint4*)(base + h * WW + w0))[q];
        int c = 4 * q;
        float2 f0 = unpack_c(t4.x), f1 = unpack_c(t4.y);
        float2 f2 = unpack_c(t4.z), f3 = unpack_c(t4.w);
        sRe[c][h]   = f0.x; sIm[c][h]   = f0.y;
        sRe[c+1][h] = f1.x; sIm[c+1][h] = f1.y;
        sRe[c+2][h] = f2.x; sIm[c+2][h] = f2.y;
        sRe[c+3][h] = f3.x; sIm[c+3][h] = f3.y;
    }
    __syncthreads();

    int warp = threadIdx.x >> 5, lane = threadIdx.x & 31;
    float2 v[10];
    #pragma unroll
    for (int j = 0; j < 10; j++) {
        int h = lane + 32 * j;
        v[j] = make_float2(sRe[warp][h], sIm[warp][h]);
    }

    fft320_fwd_t<false>(v, lane);     // skip final m=1 butterfly

    // fused L·M·L stage: v' = P*v + Q*shfl1(v)
    const char2* mrow = g_maskPQ + b * HW + (w0 + warp) * 320;
    #pragma unroll
    for (int j = 0; j < 10; j++) {
        char2 pq = mrow[lane + 32 * j];
        float P = (float)pq.x, Q = (float)pq.y;
        float ox = __shfl_xor_sync(0xffffffffu, v[j].x, 1);
        float oy = __shfl_xor_sync(0xffffffffu, v[j].y, 1);
        v[j] = make_float2(fmaf(Q, ox, P * v[j].x), fmaf(Q, oy, P * v[j].y));
    }

    fft320_inv_t<false>(v, lane);     // skip initial m=1 butterfly

    #pragma unroll
    for (int j = 0; j < 10; j++) {
        int h = lane + 32 * j;
        sRe[warp][h] = v[j].x; sIm[warp][h] = v[j].y;
    }
    __syncthreads();
    for (int pidx = threadIdx.x; pidx < 640; pidx += 256) {
        int h = pidx >> 1, q = pidx & 1;
        int c = 4 * q;
        uint4 t4;
        t4.x = pack_c(make_float2(sRe[c][h],   sIm[c][h]));
        t4.y = pack_c(make_float2(sRe[c+1][h], sIm[c+1][h]));
        t4.z = pack_c(make_float2(sRe[c+2][h], sIm[c+2][h]));
        t4.w = pack_c(make_float2(sRe[c+3][h], sIm[c+3][h]));
        ((uint4*)(base + h * WW + w0))[q] = t4;
    }
}

// ---------------- K3: inverse row FFT + conj(csm) + combine + scale + lam*p ;
//                  last block per batch computes alpha ----------------
__global__ void __launch_bounds__(256) k_inv_combine(const float* __restrict__ lam) {
    __shared__ float2 sAcc[8][320];
    int warp = threadIdx.x >> 5, lane = threadIdx.x & 31;
    int b = blockIdx.x / 320, h = blockIdx.x - b * 320;

    float2 acc[10];
    #pragma unroll
    for (int j = 0; j < 10; j++) acc[j] = make_float2(0.f, 0.f);

    #pragma unroll
    for (int cc = 0; cc < 2; cc++) {
        int bc = b * 16 + warp + 8 * cc;
        const uint2* krow2 = (const uint2*)(g_k + bc * HW + h * WW);
        float2 v[10];
        #pragma unroll
        for (int t = 0; t < 5; t++) {
            uint2 q = krow2[lane + 32 * t];
            v[2*t]   = unpack_c(q.x);
            v[2*t+1] = unpack_c(q.y);
        }
        fft320_inv(v, lane);
        const uint2* crow2 = (const uint2*)(g_csmh + bc * HW + h * WW);  // paired
        #pragma unroll
        for (int t = 0; t < 5; t++) {
            uint2 q = crow2[lane + 32 * t];
            float2 cv0 = unpack_c(q.x);
            float2 cv1 = unpack_c(q.y);
            // acc += conj(cv) * v
            acc[2*t].x   += cv0.x * v[2*t].x   + cv0.y * v[2*t].y;
            acc[2*t].y   += cv0.x * v[2*t].y   - cv0.y * v[2*t].x;
            acc[2*t+1].x += cv1.x * v[2*t+1].x + cv1.y * v[2*t+1].y;
            acc[2*t+1].y += cv1.x * v[2*t+1].y - cv1.y * v[2*t+1].x;
        }
    }
    #pragma unroll
    for (int j = 0; j < 10; j++) sAcc[warp][lane + 32 * j] = acc[j];
    __syncthreads();

    const float2* prow = g_p + b * HW + h * WW;
    float2* aprow = g_Ap + b * HW + h * WW;
    float l0 = lam[0];
    float dot = 0.f;
    for (int e = threadIdx.x; e < 320; e += 256) {
        float2 s = make_float2(0.f, 0.f);
        #pragma unroll
        for (int w = 0; w < 8; w++) { s.x += sAcc[w][e].x; s.y += sAcc[w][e].y; }
        float2 pv = prow[e];
        float2 ap = make_float2(s.x * SCALE_N2 + l0 * pv.x, s.y * SCALE_N2 + l0 * pv.y);
        aprow[e] = ap;
        dot += pv.x * ap.x + pv.y * ap.y;
    }
    float tot = block_reduce_256(dot);

    __shared__ bool isLast;
    if (threadIdx.x == 0) {
        g_partPA[blockIdx.x] = tot;   // index = b*320 + h
        __threadfence();
        unsigned c = atomicAdd(&g_cntPA[b], 1u);
        isLast = (c == HH - 1);
    }
    __syncthreads();
    if (isLast) {
        float v = 0.f;
        for (int t = threadIdx.x; t < HH; t += 256) v += g_partPA[b * HH + t];
        float s = block_reduce_256(v);
        if (threadIdx.x == 0) {
            g_alpha[b] = g_rTr[b] / s;
            g_cntPA[b] = 0;           // reset for next iteration / replay
        }
    }
}

// ---------------- K4: x += a p ; r -= a Ap ; rr partial ; last block computes beta ----------------
// first: x read skipped (x==0); last: x written to `outx` (final output) instead of g_x
__global__ void __launch_bounds__(256) k_update_xr(int first, int last, float* __restrict__ outx) {
    int b = blockIdx.x / UPD_BLKS;
    int blk = blockIdx.x - b * UPD_BLKS;
    float a = g_alpha[b];

    int e4 = b * (HW / 2) + blk * 256 + threadIdx.x;   // float4 index (2 complex)
    const float4* p4  = (const float4*)g_p;
    const float4* ap4 = (const float4*)g_Ap;
    float4* x4 = last ? (float4*)outx : (float4*)g_x;
    float4* r4 = (float4*)g_r;

    float4 pv = p4[e4], ap = ap4[e4];
    float4 xv;
    if (first) {
        xv = make_float4(a * pv.x, a * pv.y, a * pv.z, a * pv.w);
    } else {
        xv = ((const float4*)g_x)[e4];
        xv.x += a * pv.x; xv.y += a * pv.y; xv.z += a * pv.z; xv.w += a * pv.w;
    }
    x4[e4] = xv;
    float4 rv = r4[e4];
    rv.x -= a * ap.x; rv.y -= a * ap.y; rv.z -= a * ap.z; rv.w -= a * ap.w;
    r4[e4] = rv;
    float rr = rv.x * rv.x + rv.y * rv.y + rv.z * rv.z + rv.w * rv.w;
    float tot = block_reduce_256(rr);

    __shared__ bool isLast;
    if (threadIdx.x == 0) {
        g_partRR[blockIdx.x] = tot;
        __threadfence();
        unsigned c = atomicAdd(&g_cntRR[b], 1u);
        isLast = (c == UPD_BLKS - 1);
    }
    __syncthreads();
    if (isLast) {
        float v = 0.f;
        for (int t = threadIdx.x; t < UPD_BLKS; t += 256) v += g_partRR[b * UPD_BLKS + t];
        float s = block_reduce_256(v);
        if (threadIdx.x == 0) {
            g_beta[b] = s / g_rTr[b];
            g_rTr[b] = s;
            g_cntRR[b] = 0;
        }
    }
}

// ---------------- K5: p = r + beta p (float4) ----------------
__global__ void __launch_bounds__(256) k_update_p() {
    int b = blockIdx.x / UPD_BLKS;
    int blk = blockIdx.x - b * UPD_BLKS;
    float be = g_beta[b];
    int e4 = b * (HW / 2) + blk * 256 + threadIdx.x;
    const float4* r4 = (const float4*)g_r;
    float4* p4 = (float4*)g_p;
    float4 rv = r4[e4], pv = p4[e4];
    p4[e4] = make_float4(rv.x + be * pv.x, rv.y + be * pv.y,
                         rv.z + be * pv.z, rv.w + be * pv.w);
}

// ---------------- init: p=r=rhs, rr partials (float4); x not touched ----------------
__global__ void __launch_bounds__(256) k_init(const float* __restrict__ rhs) {
    int b = blockIdx.x / INIT_BLKS;
    int blk = blockIdx.x - b * INIT_BLKS;
    int i4 = blk * 256 + threadIdx.x;            // [0, 25600): float4 over real plane
    const float4* re4 = (const float4*)(rhs + (2 * b) * HW);
    const float4* im4 = (const float4*)(rhs + (2 * b + 1) * HW);
    float4 re = re4[i4], im = im4[i4];
    float4 lo = make_float4(re.x, im.x, re.y, im.y);
    float4 hi = make_float4(re.z, im.z, re.w, im.w);
    float4* p4 = (float4*)(g_p + b * HW);
    float4* r4 = (float4*)(g_r + b * HW);
    p4[2*i4] = lo; p4[2*i4+1] = hi;
    r4[2*i4] = lo; r4[2*i4+1] = hi;
    float rr = re.x*re.x + re.y*re.y + re.z*re.z + re.w*re.w
             + im.x*im.x + im.y*im.y + im.z*im.z + im.w*im.w;
    float tot = block_reduce_256(rr);
    if (threadIdx.x == 0) g_partI[blockIdx.x] = tot;
}

__global__ void __launch_bounds__(256) k_init_red() {
    int b = blockIdx.x;
    float v = 0.f;
    for (int t = threadIdx.x; t < INIT_BLKS; t += 256) v += g_partI[b * INIT_BLKS + t];
    float tot = block_reduce_256(v);
    if (threadIdx.x == 0) g_rTr[b] = tot;
}

// ---------------- launch ----------------
extern "C" void kernel_launch(void* const* d_in, const int* in_sizes, int n_in,
                              void* d_out, int out_size) {
    const float* rhs  = (const float*)d_in[0];
    const float* csm  = (const float*)d_in[1];
    const int*   mask = (const int*)d_in[2];
    const float* lam  = (const float*)d_in[3];
    float* out = (float*)d_out;

    const int FG = BATCH * NC * HH / 8;   // 5120
    const int CG = BATCH * NC * (WW / 8); // 5120
    const int IG = BATCH * HH;            // 2560
    const int UG = BATCH * UPD_BLKS;      // 1600

    k_twinit<<<2, 256>>>();
    k_csmprep<<<BATCH * NC * HW / 256, 256>>>(csm);
    k_maskprep<<<BATCH * HW / 256, 256>>>(mask);
    k_init<<<BATCH * INIT_BLKS, 256>>>(rhs);
    k_init_red<<<BATCH, 256>>>();

    for (int it = 0; it < NITER; it++) {
        k_rows_fwd<<<FG, 256>>>();
        k_cols<<<CG, 256>>>();
        k_inv_combine<<<IG, 256>>>(lam);
        k_update_xr<<<UG, 256>>>(it == 0 ? 1 : 0, it == NITER - 1 ? 1 : 0, out);
        if (it < NITER - 1) k_update_p<<<UG, 256>>>();
    }
}

// round 16
// speedup vs baseline: 1.0457x; 1.0057x over previous
#include <cuda_runtime.h>
#include <cuda_fp16.h>
#include <math.h>

// Problem constants
#define BATCH 8
#define NC    16
#define HH    320
#define WW    320
#define HW    102400
#define NITER 10
#define INIT_BLKS 100   // blocks/batch in k_init
#define UPD_BLKS  200   // blocks/batch in update kernels
#define SCALE_N2 (1.0f / 102400.0f)

// ---------------- scratch (device globals; no runtime allocation) ----------------
__device__ __align__(16) __half2 g_k[BATCH * NC * HW];   // coil k-space, fp16 complex (paired permuted layout)
__device__ __align__(16) __half2 g_csmh[BATCH * NC * HW];// csm fp16 complex, PAIRED layout (written by first rows_fwd)
__device__ __align__(16) float2 g_x[BATCH * HW];
__device__ __align__(16) float2 g_r[BATCH * HW];
__device__ __align__(16) float2 g_p[BATCH * HW];
__device__ __align__(16) float2 g_Ap[BATCH * HW];
__device__ __align__(16) char2 g_maskPQ[BATCH * HW];    // (P, Q) pairs for fused mask stage
__device__ float  g_partPA[BATCH * HH];                 // p.Ap partials
__device__ float  g_partRR[BATCH * UPD_BLKS];           // r.r partials
__device__ float  g_partI[BATCH * INIT_BLKS];           // init rr partials
__device__ float  g_rTr[BATCH];
__device__ float  g_alpha[BATCH];
__device__ float  g_beta[BATCH];
__device__ unsigned g_cntPA[BATCH];                     // last-block counters (self-resetting)
__device__ unsigned g_cntRR[BATCH];
__device__ unsigned g_cntI[BATCH];
__device__ float2 g_tw320[288];           // exp(-2pi i k*lane/320), k=1..9
__device__ float2 g_tw32[128];            // fft32 stage twiddles; DOWN lanes hold (1,0)

// ---------------- complex helpers ----------------
__device__ __forceinline__ float2 cmul(float2 a, float2 b) {
    return make_float2(a.x*b.x - a.y*b.y, a.x*b.y + a.y*b.x);
}
__device__ __forceinline__ float2 cadd(float2 a, float2 b) { return make_float2(a.x+b.x, a.y+b.y); }
__device__ __forceinline__ float2 csub(float2 a, float2 b) { return make_float2(a.x-b.x, a.y-b.y); }
__device__ __forceinline__ int br5(int l) { return (int)(__brev((unsigned)l) >> 27); }

__device__ __forceinline__ unsigned pack_c(float2 v) {
    __half2 h = __floats2half2_rn(v.x, v.y);
    return *(unsigned*)&h;
}
__device__ __forceinline__ float2 unpack_c(unsigned u) {
    __half2 h = *(__half2*)&u;
    return __half22float2(h);
}

// ---------------- radix-5 ----------------
#define C51 0.30901699437494745f
#define C52 (-0.8090169943749475f)
#define S51 0.9510565162951535f
#define S52 0.5877852522924731f

template<int DIR>
__device__ __forceinline__ void fft5(float2 a0, float2 a1, float2 a2, float2 a3, float2 a4,
                                     float2& b0, float2& b1, float2& b2, float2& b3, float2& b4) {
    const float dir = (float)DIR;
    float2 t1 = cadd(a1, a4), t2 = cadd(a2, a3);
    float2 t3 = csub(a1, a4), t4 = csub(a2, a3);
    float2 m1 = make_float2(a0.x + C51*t1.x + C52*t2.x, a0.y + C51*t1.y + C52*t2.y);
    float2 m2 = make_float2(a0.x + C52*t1.x + C51*t2.x, a0.y + C52*t1.y + C51*t2.y);
    float2 u1 = make_float2(S51*t3.x + S52*t4.x, S51*t3.y + S52*t4.y);
    float2 u2 = make_float2(S52*t3.x - S51*t4.x, S52*t3.y - S51*t4.y);
    b0 = make_float2(a0.x + t1.x + t2.x, a0.y + t1.y + t2.y);
    b1 = make_float2(m1.x - dir*u1.y, m1.y + dir*u1.x);
    b4 = make_float2(m1.x + dir*u1.y, m1.y - dir*u1.x);
    b2 = make_float2(m2.x - dir*u2.y, m2.y + dir*u2.x);
    b3 = make_float2(m2.x + dir*u2.y, m2.y - dir*u2.x);
}

// ---------------- per-lane 10-point FFT ----------------
template<int DIR>
__device__ __forceinline__ void fft10(float2 v[10]) {
    const float dir = (float)DIR;
    float2 e0,e1,e2,e3,e4, o0,o1,o2,o3,o4;
    fft5<DIR>(v[0], v[2], v[4], v[6], v[8], e0, e1, e2, e3, e4);
    fft5<DIR>(v[1], v[3], v[5], v[7], v[9], o0, o1, o2, o3, o4);
    const float c1 = 0.80901699437494745f, s1 = 0.58778525229247314f;
    const float c2 = 0.30901699437494745f, s2 = 0.95105651629515357f;
    float2 t;
    v[0] = cadd(e0, o0);                       v[5] = csub(e0, o0);
    t = cmul(o1, make_float2( c1, dir*s1));    v[1] = cadd(e1, t); v[6] = csub(e1, t);
    t = cmul(o2, make_float2( c2, dir*s2));    v[2] = cadd(e2, t); v[7] = csub(e2, t);
    t = cmul(o3, make_float2(-c2, dir*s2));    v[3] = cadd(e3, t); v[8] = csub(e3, t);
    t = cmul(o4, make_float2(-c1, dir*s1));    v[4] = cadd(e4, t); v[9] = csub(e4, t);
}

// ---------------- full 320-pt forward; LAST=false skips final m=1 butterfly ----------------
template<bool LAST>
__device__ __forceinline__ void fft320_fwd_t(float2 v[10], int lane) {
    fft10<-1>(v);
    #pragma unroll
    for (int k = 1; k < 10; k++) v[k] = cmul(v[k], g_tw320[(k-1)*32 + lane]);
    #pragma unroll
    for (int s = 0; s < 4; s++) {
        int m = 16 >> s;
        float2 w = g_tw32[s*32 + lane];           // (1,0) on down lanes
        float sg = (lane & m) ? -1.f : 1.f;
        #pragma unroll
        for (int r = 0; r < 10; r++) {
            float ox = __shfl_xor_sync(0xffffffffu, v[r].x, m);
            float oy = __shfl_xor_sync(0xffffffffu, v[r].y, m);
            float tx = fmaf(sg, v[r].x, ox);
            float ty = fmaf(sg, v[r].y, oy);
            v[r] = cmul(make_float2(tx, ty), w);
        }
    }
    if (LAST) {
        float sg1 = (lane & 1) ? -1.f : 1.f;      // m=1: no twiddle
        #pragma unroll
        for (int r = 0; r < 10; r++) {
            float ox = __shfl_xor_sync(0xffffffffu, v[r].x, 1);
            float oy = __shfl_xor_sync(0xffffffffu, v[r].y, 1);
            v[r] = make_float2(fmaf(sg1, v[r].x, ox), fmaf(sg1, v[r].y, oy));
        }
    }
}
__device__ __forceinline__ void fft320_fwd(float2 v[10], int lane) { fft320_fwd_t<true>(v, lane); }

// ---------------- full 320-pt inverse (unnormalized); FIRST=false skips initial m=1 butterfly ----------------
template<bool FIRST>
__device__ __forceinline__ void fft320_inv_t(float2 v[10], int lane) {
    if (FIRST) {
        float sg1 = (lane & 1) ? -1.f : 1.f;      // m=1: no twiddle
        #pragma unroll
        for (int r = 0; r < 10; r++) {
            float ox = __shfl_xor_sync(0xffffffffu, v[r].x, 1);
            float oy = __shfl_xor_sync(0xffffffffu, v[r].y, 1);
            v[r] = make_float2(fmaf(sg1, v[r].x, ox), fmaf(sg1, v[r].y, oy));
        }
    }
    #pragma unroll
    for (int s = 3; s >= 0; s--) {
        int m = 16 >> s;
        float2 wf = g_tw32[s*32 + lane];
        float2 w = make_float2(wf.x, -wf.y);      // conj
        float sg = (lane & m) ? -1.f : 1.f;
        #pragma unroll
        for (int r = 0; r < 10; r++) {
            float2 u = cmul(v[r], w);             // pre-twiddle (unit on down lanes)
            float ox = __shfl_xor_sync(0xffffffffu, u.x, m);
            float oy = __shfl_xor_sync(0xffffffffu, u.y, m);
            v[r] = make_float2(fmaf(sg, u.x, ox), fmaf(sg, u.y, oy));
        }
    }
    #pragma unroll
    for (int k = 1; k < 10; k++) {
        float2 wf = g_tw320[(k-1)*32 + lane];
        v[k] = cmul(v[k], make_float2(wf.x, -wf.y));
    }
    fft10<+1>(v);
}
__device__ __forceinline__ void fft320_inv(float2 v[10], int lane) { fft320_inv_t<true>(v, lane); }

// ---------------- block reduction (deterministic tree) ----------------
__device__ __forceinline__ float block_reduce_256(float v) {
    __shared__ float red[256];
    red[threadIdx.x] = v;
    __syncthreads();
    #pragma unroll
    for (int s = 128; s > 0; s >>= 1) {
        if (threadIdx.x < s) red[threadIdx.x] += red[threadIdx.x + s];
        __syncthreads();
    }
    return red[0];
}

// ---------------- twiddle table init (one-time per call, exact) ----------------
__global__ void __launch_bounds__(256) k_twinit() {
    int t = blockIdx.x * 256 + threadIdx.x;
    if (t < 288) {
        int k = t / 32 + 1, l = t & 31;
        double a = -2.0 * M_PI * (double)(k * l) / 320.0;
        double s, c; sincos(a, &s, &c);
        g_tw320[t] = make_float2((float)c, (float)s);
    } else if (t < 416) {
        int u = t - 288;
        int s2 = u >> 5, l = u & 31;
        int m = 16 >> s2;
        if (l & m) {                      // up lanes: real stage twiddle
            int j = l & (m - 1);
            double a = -M_PI * (double)j / (double)m;
            double ss, cc; sincos(a, &ss, &cc);
            g_tw32[u] = make_float2((float)cc, (float)ss);
        } else {                          // down lanes: unit twiddle
            g_tw32[u] = make_float2(1.f, 0.f);
        }
    }
}

// ---------------- mask prep: (P, Q) pairs for the fused L·M·L stage ----------------
__global__ void __launch_bounds__(256) k_maskprep(const int* __restrict__ mask) {
    int e = blockIdx.x * 256 + threadIdx.x;      // [0, B*HW)
    int b = e / HW; int rem = e - b * HW;
    int w_mem = rem / 320; int idx = rem - w_mem * 320;
    int l = idx & 31, j = idx >> 5;
    int hfreq_own = 10 * br5(l) + j;
    int hfreq_par = 10 * br5(l ^ 1) + j;
    int wl = (w_mem >> 1) & 31, ws = w_mem & 1, wt = w_mem >> 6;
    int wfreq = 10 * br5(wl) + 2 * wt + ws;
    int m_own = mask[b * HW + hfreq_own * 320 + wfreq];
    int m_par = mask[b * HW + hfreq_par * 320 + wfreq];
    int P = m_own + m_par;
    int Q = (l & 1) ? (m_par - m_own) : (m_own - m_par);
    g_maskPQ[e] = make_char2((char)P, (char)Q);
}

// ---------------- K1: coil = csm*p ; forward row FFT ; fp16 paired stores ----------------
// first!=0: convert fp32 csm -> fp16 paired inline (writes g_csmh); values used are the
// SAME RN-rounded fp16 values as later iterations (bit-identical arithmetic).
__global__ void __launch_bounds__(256) k_rows_fwd(const float* __restrict__ csm, int first) {
    int warp = threadIdx.x >> 5, lane = threadIdx.x & 31;
    int row = blockIdx.x * 8 + warp;          // bc*320 + h
    int bc = row / 320, h = row - bc * 320;
    int b = bc >> 4;
    const float2* prow = g_p + b * HW + h * WW;
    float2 v[10];
    if (first) {
        const float2* cn = (const float2*)csm + bc * HW + h * WW;   // natural layout
        uint2* cw = (uint2*)(g_csmh + bc * HW + h * WW);            // paired layout
        #pragma unroll
        for (int t = 0; t < 5; t++) {
            float2 a0 = cn[lane + 64 * t];          // natural j = 2t
            float2 a1 = cn[lane + 64 * t + 32];     // natural j = 2t+1
            unsigned q0 = pack_c(a0), q1 = pack_c(a1);
            cw[lane + 32 * t] = make_uint2(q0, q1);
            float2 cv0 = unpack_c(q0);
            float2 cv1 = unpack_c(q1);
            v[2*t]   = cmul(cv0, prow[lane + 32 * (2*t)]);
            v[2*t+1] = cmul(cv1, prow[lane + 32 * (2*t+1)]);
        }
    } else {
        const uint2* crow2 = (const uint2*)(g_csmh + bc * HW + h * WW);
        #pragma unroll
        for (int t = 0; t < 5; t++) {
            uint2 q = crow2[lane + 32 * t];
            float2 cv0 = unpack_c(q.x);
            float2 cv1 = unpack_c(q.y);
            v[2*t]   = cmul(cv0, prow[lane + 32 * (2*t)]);
            v[2*t+1] = cmul(cv1, prow[lane + 32 * (2*t+1)]);
        }
    }
    fft320_fwd(v, lane);
    uint2* out2 = (uint2*)(g_k + bc * HW + h * WW);
    #pragma unroll
    for (int t = 0; t < 5; t++) {
        uint2 q;
        q.x = pack_c(v[2*t]);
        q.y = pack_c(v[2*t+1]);
        out2[lane + 32 * t] = q;
    }
}

// ---------------- K2: column FFT + fused mask stage + column IFFT (split fp32 SMEM staging) ----------------
__global__ void __launch_bounds__(256) k_cols() {
    __shared__ float sRe[8][324];
    __shared__ float sIm[8][324];
    int bc = blockIdx.x / 40;
    int w0 = (blockIdx.x - bc * 40) * 8;
    int b = bc >> 4;
    __half2* base = g_k + bc * HW;

    for (int pidx = threadIdx.x; pidx < 640; pidx += 256) {
        int h = pidx >> 1, q = pidx & 1;
        uint4 t4 = ((const uint4*)(base + h * WW + w0))[q];
        int c = 4 * q;
        float2 f0 = unpack_c(t4.x), f1 = unpack_c(t4.y);
        float2 f2 = unpack_c(t4.z), f3 = unpack_c(t4.w);
        sRe[c][h]   = f0.x; sIm[c][h]   = f0.y;
        sRe[c+1][h] = f1.x; sIm[c+1][h] = f1.y;
        sRe[c+2][h] = f2.x; sIm[c+2][h] = f2.y;
        sRe[c+3][h] = f3.x; sIm[c+3][h] = f3.y;
    }
    __syncthreads();

    int warp = threadIdx.x >> 5, lane = threadIdx.x & 31;
    float2 v[10];
    #pragma unroll
    for (int j = 0; j < 10; j++) {
        int h = lane + 32 * j;
        v[j] = make_float2(sRe[warp][h], sIm[warp][h]);
    }

    fft320_fwd_t<false>(v, lane);     // skip final m=1 butterfly

    // fused L·M·L stage: v' = P*v + Q*shfl1(v)
    const char2* mrow = g_maskPQ + b * HW + (w0 + warp) * 320;
    #pragma unroll
    for (int j = 0; j < 10; j++) {
        char2 pq = mrow[lane + 32 * j];
        float P = (float)pq.x, Q = (float)pq.y;
        float ox = __shfl_xor_sync(0xffffffffu, v[j].x, 1);
        float oy = __shfl_xor_sync(0xffffffffu, v[j].y, 1);
        v[j] = make_float2(fmaf(Q, ox, P * v[j].x), fmaf(Q, oy, P * v[j].y));
    }

    fft320_inv_t<false>(v, lane);     // skip initial m=1 butterfly

    #pragma unroll
    for (int j = 0; j < 10; j++) {
        int h = lane + 32 * j;
        sRe[warp][h] = v[j].x; sIm[warp][h] = v[j].y;
    }
    __syncthreads();
    for (int pidx = threadIdx.x; pidx < 640; pidx += 256) {
        int h = pidx >> 1, q = pidx & 1;
        int c = 4 * q;
        uint4 t4;
        t4.x = pack_c(make_float2(sRe[c][h],   sIm[c][h]));
        t4.y = pack_c(make_float2(sRe[c+1][h], sIm[c+1][h]));
        t4.z = pack_c(make_float2(sRe[c+2][h], sIm[c+2][h]));
        t4.w = pack_c(make_float2(sRe[c+3][h], sIm[c+3][h]));
        ((uint4*)(base + h * WW + w0))[q] = t4;
    }
}

// ---------------- K3: inverse row FFT + conj(csm) + combine + scale + lam*p ;
//                  last block per batch computes alpha ----------------
__global__ void __launch_bounds__(256) k_inv_combine(const float* __restrict__ lam) {
    __shared__ float2 sAcc[8][320];
    int warp = threadIdx.x >> 5, lane = threadIdx.x & 31;
    int b = blockIdx.x / 320, h = blockIdx.x - b * 320;

    float2 acc[10];
    #pragma unroll
    for (int j = 0; j < 10; j++) acc[j] = make_float2(0.f, 0.f);

    #pragma unroll
    for (int cc = 0; cc < 2; cc++) {
        int bc = b * 16 + warp + 8 * cc;
        const uint2* krow2 = (const uint2*)(g_k + bc * HW + h * WW);
        float2 v[10];
        #pragma unroll
        for (int t = 0; t < 5; t++) {
            uint2 q = krow2[lane + 32 * t];
            v[2*t]   = unpack_c(q.x);
            v[2*t+1] = unpack_c(q.y);
        }
        fft320_inv(v, lane);
        const uint2* crow2 = (const uint2*)(g_csmh + bc * HW + h * WW);  // paired
        #pragma unroll
        for (int t = 0; t < 5; t++) {
            uint2 q = crow2[lane + 32 * t];
            float2 cv0 = unpack_c(q.x);
            float2 cv1 = unpack_c(q.y);
            // acc += conj(cv) * v
            acc[2*t].x   += cv0.x * v[2*t].x   + cv0.y * v[2*t].y;
            acc[2*t].y   += cv0.x * v[2*t].y   - cv0.y * v[2*t].x;
            acc[2*t+1].x += cv1.x * v[2*t+1].x + cv1.y * v[2*t+1].y;
            acc[2*t+1].y += cv1.x * v[2*t+1].y - cv1.y * v[2*t+1].x;
        }
    }
    #pragma unroll
    for (int j = 0; j < 10; j++) sAcc[warp][lane + 32 * j] = acc[j];
    __syncthreads();

    const float2* prow = g_p + b * HW + h * WW;
    float2* aprow = g_Ap + b * HW + h * WW;
    float l0 = lam[0];
    float dot = 0.f;
    for (int e = threadIdx.x; e < 320; e += 256) {
        float2 s = make_float2(0.f, 0.f);
        #pragma unroll
        for (int w = 0; w < 8; w++) { s.x += sAcc[w][e].x; s.y += sAcc[w][e].y; }
        float2 pv = prow[e];
        float2 ap = make_float2(s.x * SCALE_N2 + l0 * pv.x, s.y * SCALE_N2 + l0 * pv.y);
        aprow[e] = ap;
        dot += pv.x * ap.x + pv.y * ap.y;
    }
    float tot = block_reduce_256(dot);

    __shared__ bool isLast;
    if (threadIdx.x == 0) {
        g_partPA[blockIdx.x] = tot;   // index = b*320 + h
        __threadfence();
        unsigned c = atomicAdd(&g_cntPA[b], 1u);
        isLast = (c == HH - 1);
    }
    __syncthreads();
    if (isLast) {
        float v = 0.f;
        for (int t = threadIdx.x; t < HH; t += 256) v += g_partPA[b * HH + t];
        float s = block_reduce_256(v);
        if (threadIdx.x == 0) {
            g_alpha[b] = g_rTr[b] / s;
            g_cntPA[b] = 0;           // reset for next iteration / replay
        }
    }
}

// ---------------- K4: x += a p ; r -= a Ap ; rr partial ; last block computes beta ----------------
// first: x read skipped (x==0); last: x written to `outx` (final output) instead of g_x
__global__ void __launch_bounds__(256) k_update_xr(int first, int last, float* __restrict__ outx) {
    int b = blockIdx.x / UPD_BLKS;
    int blk = blockIdx.x - b * UPD_BLKS;
    float a = g_alpha[b];

    int e4 = b * (HW / 2) + blk * 256 + threadIdx.x;   // float4 index (2 complex)
    const float4* p4  = (const float4*)g_p;
    const float4* ap4 = (const float4*)g_Ap;
    float4* x4 = last ? (float4*)outx : (float4*)g_x;
    float4* r4 = (float4*)g_r;

    float4 pv = p4[e4], ap = ap4[e4];
    float4 xv;
    if (first) {
        xv = make_float4(a * pv.x, a * pv.y, a * pv.z, a * pv.w);
    } else {
        xv = ((const float4*)g_x)[e4];
        xv.x += a * pv.x; xv.y += a * pv.y; xv.z += a * pv.z; xv.w += a * pv.w;
    }
    x4[e4] = xv;
    float4 rv = r4[e4];
    rv.x -= a * ap.x; rv.y -= a * ap.y; rv.z -= a * ap.z; rv.w -= a * ap.w;
    r4[e4] = rv;
    float rr = rv.x * rv.x + rv.y * rv.y + rv.z * rv.z + rv.w * rv.w;
    float tot = block_reduce_256(rr);

    __shared__ bool isLast;
    if (threadIdx.x == 0) {
        g_partRR[blockIdx.x] = tot;
        __threadfence();
        unsigned c = atomicAdd(&g_cntRR[b], 1u);
        isLast = (c == UPD_BLKS - 1);
    }
    __syncthreads();
    if (isLast) {
        float v = 0.f;
        for (int t = threadIdx.x; t < UPD_BLKS; t += 256) v += g_partRR[b * UPD_BLKS + t];
        float s = block_reduce_256(v);
        if (threadIdx.x == 0) {
            g_beta[b] = s / g_rTr[b];
            g_rTr[b] = s;
            g_cntRR[b] = 0;
        }
    }
}

// ---------------- K5: p = r + beta p (float4) ----------------
__global__ void __launch_bounds__(256) k_update_p() {
    int b = blockIdx.x / UPD_BLKS;
    int blk = blockIdx.x - b * UPD_BLKS;
    float be = g_beta[b];
    int e4 = b * (HW / 2) + blk * 256 + threadIdx.x;
    const float4* r4 = (const float4*)g_r;
    float4* p4 = (float4*)g_p;
    float4 rv = r4[e4], pv = p4[e4];
    p4[e4] = make_float4(rv.x + be * pv.x, rv.y + be * pv.y,
                         rv.z + be * pv.z, rv.w + be * pv.w);
}

// ---------------- init: p=r=rhs, rr partials ; last block per batch reduces rTr ----------------
__global__ void __launch_bounds__(256) k_init(const float* __restrict__ rhs) {
    int b = blockIdx.x / INIT_BLKS;
    int blk = blockIdx.x - b * INIT_BLKS;
    int i4 = blk * 256 + threadIdx.x;            // [0, 25600): float4 over real plane
    const float4* re4 = (const float4*)(rhs + (2 * b) * HW);
    const float4* im4 = (const float4*)(rhs + (2 * b + 1) * HW);
    float4 re = re4[i4], im = im4[i4];
    float4 lo = make_float4(re.x, im.x, re.y, im.y);
    float4 hi = make_float4(re.z, im.z, re.w, im.w);
    float4* p4 = (float4*)(g_p + b * HW);
    float4* r4 = (float4*)(g_r + b * HW);
    p4[2*i4] = lo; p4[2*i4+1] = hi;
    r4[2*i4] = lo; r4[2*i4+1] = hi;
    float rr = re.x*re.x + re.y*re.y + re.z*re.z + re.w*re.w
             + im.x*im.x + im.y*im.y + im.z*im.z + im.w*im.w;
    float tot = block_reduce_256(rr);

    __shared__ bool isLast;
    if (threadIdx.x == 0) {
        g_partI[blockIdx.x] = tot;
        __threadfence();
        unsigned c = atomicAdd(&g_cntI[b], 1u);
        isLast = (c == INIT_BLKS - 1);
    }
    __syncthreads();
    if (isLast) {
        float v = 0.f;
        for (int t = threadIdx.x; t < INIT_BLKS; t += 256) v += g_partI[b * INIT_BLKS + t];
        float s = block_reduce_256(v);
        if (threadIdx.x == 0) {
            g_rTr[b] = s;
            g_cntI[b] = 0;            // reset for replay
        }
    }
}

// ---------------- launch ----------------
extern "C" void kernel_launch(void* const* d_in, const int* in_sizes, int n_in,
                              void* d_out, int out_size) {
    const float* rhs  = (const float*)d_in[0];
    const float* csm  = (const float*)d_in[1];
    const int*   mask = (const int*)d_in[2];
    const float* lam  = (const float*)d_in[3];
    float* out = (float*)d_out;

    const int FG = BATCH * NC * HH / 8;   // 5120
    const int CG = BATCH * NC * (WW / 8); // 5120
    const int IG = BATCH * HH;            // 2560
    const int UG = BATCH * UPD_BLKS;      // 1600

    k_twinit<<<2, 256>>>();
    k_maskprep<<<BATCH * HW / 256, 256>>>(mask);
    k_init<<<BATCH * INIT_BLKS, 256>>>(rhs);

    for (int it = 0; it < NITER; it++) {
        k_rows_fwd<<<FG, 256>>>(csm, it == 0 ? 1 : 0);
        k_cols<<<CG, 256>>>();
        k_inv_combine<<<IG, 256>>>(lam);
        k_update_xr<<<UG, 256>>>(it == 0 ? 1 : 0, it == NITER - 1 ? 1 : 0, out);
        if (it < NITER - 1) k_update_p<<<UG, 256>>>();
    }
}

// round 17
// speedup vs baseline: 1.0577x; 1.0115x over previous
#include <cuda_runtime.h>
#include <cuda_fp16.h>
#include <math.h>

// Problem constants
#define BATCH 8
#define NC    16
#define HH    320
#define WW    320
#define HW    102400
#define NITER 10
#define INIT_BLKS 100   // blocks/batch in k_init
#define UPD_BLKS  200   // blocks/batch in update kernels
#define SCALE_N2 (1.0f / 102400.0f)

// ---------------- scratch (device globals; no runtime allocation) ----------------
__device__ __align__(16) __half2 g_k[BATCH * NC * HW];   // coil k-space, fp16 complex (paired permuted layout)
__device__ __align__(16) __half2 g_csmh[BATCH * NC * HW];// csm fp16 complex, PAIRED layout (written by first rows_fwd)
__device__ __align__(16) float2 g_x[BATCH * HW];
__device__ __align__(16) float2 g_r[BATCH * HW];
__device__ __align__(16) float2 g_p[BATCH * HW];
__device__ __align__(16) float2 g_Ap[BATCH * HW];
__device__ __align__(16) char2 g_maskPQ[BATCH * HW];    // (P, Q) pairs for fused mask stage
__device__ float  g_partPA[BATCH * HH];                 // p.Ap partials
__device__ float  g_partRR[BATCH * UPD_BLKS];           // r.r partials
__device__ float  g_partI[BATCH * INIT_BLKS];           // init rr partials
__device__ float  g_rTr[BATCH];
__device__ float  g_alpha[BATCH];
__device__ float  g_beta[BATCH];
__device__ unsigned g_cntPA[BATCH];                     // last-block counters (self-resetting)
__device__ unsigned g_cntRR[BATCH];
__device__ unsigned g_cntI[BATCH];
__device__ float2 g_tw320[288];           // exp(-2pi i k*lane/320), k=1..9
__device__ float2 g_tw32[128];            // fft32 stage twiddles; DOWN lanes hold (1,0)

// ---------------- complex helpers ----------------
__device__ __forceinline__ float2 cmul(float2 a, float2 b) {
    return make_float2(a.x*b.x - a.y*b.y, a.x*b.y + a.y*b.x);
}
__device__ __forceinline__ float2 cadd(float2 a, float2 b) { return make_float2(a.x+b.x, a.y+b.y); }
__device__ __forceinline__ float2 csub(float2 a, float2 b) { return make_float2(a.x-b.x, a.y-b.y); }
__device__ __forceinline__ int br5(int l) { return (int)(__brev((unsigned)l) >> 27); }

__device__ __forceinline__ unsigned pack_c(float2 v) {
    __half2 h = __floats2half2_rn(v.x, v.y);
    return *(unsigned*)&h;
}
__device__ __forceinline__ float2 unpack_c(unsigned u) {
    __half2 h = *(__half2*)&u;
    return __half22float2(h);
}

// ---------------- radix-5 ----------------
#define C51 0.30901699437494745f
#define C52 (-0.8090169943749475f)
#define S51 0.9510565162951535f
#define S52 0.5877852522924731f

template<int DIR>
__device__ __forceinline__ void fft5(float2 a0, float2 a1, float2 a2, float2 a3, float2 a4,
                                     float2& b0, float2& b1, float2& b2, float2& b3, float2& b4) {
    const float dir = (float)DIR;
    float2 t1 = cadd(a1, a4), t2 = cadd(a2, a3);
    float2 t3 = csub(a1, a4), t4 = csub(a2, a3);
    float2 m1 = make_float2(a0.x + C51*t1.x + C52*t2.x, a0.y + C51*t1.y + C52*t2.y);
    float2 m2 = make_float2(a0.x + C52*t1.x + C51*t2.x, a0.y + C52*t1.y + C51*t2.y);
    float2 u1 = make_float2(S51*t3.x + S52*t4.x, S51*t3.y + S52*t4.y);
    float2 u2 = make_float2(S52*t3.x - S51*t4.x, S52*t3.y - S51*t4.y);
    b0 = make_float2(a0.x + t1.x + t2.x, a0.y + t1.y + t2.y);
    b1 = make_float2(m1.x - dir*u1.y, m1.y + dir*u1.x);
    b4 = make_float2(m1.x + dir*u1.y, m1.y - dir*u1.x);
    b2 = make_float2(m2.x - dir*u2.y, m2.y + dir*u2.x);
    b3 = make_float2(m2.x + dir*u2.y, m2.y - dir*u2.x);
}

// ---------------- per-lane 10-point FFT ----------------
template<int DIR>
__device__ __forceinline__ void fft10(float2 v[10]) {
    const float dir = (float)DIR;
    float2 e0,e1,e2,e3,e4, o0,o1,o2,o3,o4;
    fft5<DIR>(v[0], v[2], v[4], v[6], v[8], e0, e1, e2, e3, e4);
    fft5<DIR>(v[1], v[3], v[5], v[7], v[9], o0, o1, o2, o3, o4);
    const float c1 = 0.80901699437494745f, s1 = 0.58778525229247314f;
    const float c2 = 0.30901699437494745f, s2 = 0.95105651629515357f;
    float2 t;
    v[0] = cadd(e0, o0);                       v[5] = csub(e0, o0);
    t = cmul(o1, make_float2( c1, dir*s1));    v[1] = cadd(e1, t); v[6] = csub(e1, t);
    t = cmul(o2, make_float2( c2, dir*s2));    v[2] = cadd(e2, t); v[7] = csub(e2, t);
    t = cmul(o3, make_float2(-c2, dir*s2));    v[3] = cadd(e3, t); v[8] = csub(e3, t);
    t = cmul(o4, make_float2(-c1, dir*s1));    v[4] = cadd(e4, t); v[9] = csub(e4, t);
}

// ---------------- full 320-pt forward; LAST=false skips final m=1 butterfly ----------------
template<bool LAST>
__device__ __forceinline__ void fft320_fwd_t(float2 v[10], int lane) {
    fft10<-1>(v);
    #pragma unroll
    for (int k = 1; k < 10; k++) v[k] = cmul(v[k], g_tw320[(k-1)*32 + lane]);
    #pragma unroll
    for (int s = 0; s < 4; s++) {
        int m = 16 >> s;
        float2 w = g_tw32[s*32 + lane];           // (1,0) on down lanes
        float sg = (lane & m) ? -1.f : 1.f;
        #pragma unroll
        for (int r = 0; r < 10; r++) {
            float ox = __shfl_xor_sync(0xffffffffu, v[r].x, m);
            float oy = __shfl_xor_sync(0xffffffffu, v[r].y, m);
            float tx = fmaf(sg, v[r].x, ox);
            float ty = fmaf(sg, v[r].y, oy);
            v[r] = cmul(make_float2(tx, ty), w);
        }
    }
    if (LAST) {
        float sg1 = (lane & 1) ? -1.f : 1.f;      // m=1: no twiddle
        #pragma unroll
        for (int r = 0; r < 10; r++) {
            float ox = __shfl_xor_sync(0xffffffffu, v[r].x, 1);
            float oy = __shfl_xor_sync(0xffffffffu, v[r].y, 1);
            v[r] = make_float2(fmaf(sg1, v[r].x, ox), fmaf(sg1, v[r].y, oy));
        }
    }
}
__device__ __forceinline__ void fft320_fwd(float2 v[10], int lane) { fft320_fwd_t<true>(v, lane); }

// ---------------- full 320-pt inverse (unnormalized); FIRST=false skips initial m=1 butterfly ----------------
template<bool FIRST>
__device__ __forceinline__ void fft320_inv_t(float2 v[10], int lane) {
    if (FIRST) {
        float sg1 = (lane & 1) ? -1.f : 1.f;      // m=1: no twiddle
        #pragma unroll
        for (int r = 0; r < 10; r++) {
            float ox = __shfl_xor_sync(0xffffffffu, v[r].x, 1);
            float oy = __shfl_xor_sync(0xffffffffu, v[r].y, 1);
            v[r] = make_float2(fmaf(sg1, v[r].x, ox), fmaf(sg1, v[r].y, oy));
        }
    }
    #pragma unroll
    for (int s = 3; s >= 0; s--) {
        int m = 16 >> s;
        float2 wf = g_tw32[s*32 + lane];
        float2 w = make_float2(wf.x, -wf.y);      // conj
        float sg = (lane & m) ? -1.f : 1.f;
        #pragma unroll
        for (int r = 0; r < 10; r++) {
            float2 u = cmul(v[r], w);             // pre-twiddle (unit on down lanes)
            float ox = __shfl_xor_sync(0xffffffffu, u.x, m);
            float oy = __shfl_xor_sync(0xffffffffu, u.y, m);
            v[r] = make_float2(fmaf(sg, u.x, ox), fmaf(sg, u.y, oy));
        }
    }
    #pragma unroll
    for (int k = 1; k < 10; k++) {
        float2 wf = g_tw320[(k-1)*32 + lane];
        v[k] = cmul(v[k], make_float2(wf.x, -wf.y));
    }
    fft10<+1>(v);
}
__device__ __forceinline__ void fft320_inv(float2 v[10], int lane) { fft320_inv_t<true>(v, lane); }

// ---------------- block reduction (deterministic tree) ----------------
__device__ __forceinline__ float block_reduce_256(float v) {
    __shared__ float red[256];
    red[threadIdx.x] = v;
    __syncthreads();
    #pragma unroll
    for (int s = 128; s > 0; s >>= 1) {
        if (threadIdx.x < s) red[threadIdx.x] += red[threadIdx.x + s];
        __syncthreads();
    }
    return red[0];
}

// ---------------- twiddle table init (one-time per call, exact) ----------------
__global__ void __launch_bounds__(256) k_twinit() {
    int t = blockIdx.x * 256 + threadIdx.x;
    if (t < 288) {
        int k = t / 32 + 1, l = t & 31;
        double a = -2.0 * M_PI * (double)(k * l) / 320.0;
        double s, c; sincos(a, &s, &c);
        g_tw320[t] = make_float2((float)c, (float)s);
    } else if (t < 416) {
        int u = t - 288;
        int s2 = u >> 5, l = u & 31;
        int m = 16 >> s2;
        if (l & m) {                      // up lanes: real stage twiddle
            int j = l & (m - 1);
            double a = -M_PI * (double)j / (double)m;
            double ss, cc; sincos(a, &ss, &cc);
            g_tw32[u] = make_float2((float)cc, (float)ss);
        } else {                          // down lanes: unit twiddle
            g_tw32[u] = make_float2(1.f, 0.f);
        }
    }
}

// ---------------- mask prep: (P, Q) pairs for the fused L·M·L stage ----------------
__global__ void __launch_bounds__(256) k_maskprep(const int* __restrict__ mask) {
    int e = blockIdx.x * 256 + threadIdx.x;      // [0, B*HW)
    int b = e / HW; int rem = e - b * HW;
    int w_mem = rem / 320; int idx = rem - w_mem * 320;
    int l = idx & 31, j = idx >> 5;
    int hfreq_own = 10 * br5(l) + j;
    int hfreq_par = 10 * br5(l ^ 1) + j;
    int wl = (w_mem >> 1) & 31, ws = w_mem & 1, wt = w_mem >> 6;
    int wfreq = 10 * br5(wl) + 2 * wt + ws;
    int m_own = mask[b * HW + hfreq_own * 320 + wfreq];
    int m_par = mask[b * HW + hfreq_par * 320 + wfreq];
    int P = m_own + m_par;
    int Q = (l & 1) ? (m_par - m_own) : (m_own - m_par);
    g_maskPQ[e] = make_char2((char)P, (char)Q);
}

// ---------------- K1: coil = csm*p ; forward row FFT ; fp16 paired stores ----------------
// first!=0: convert fp32 csm -> fp16 paired inline (writes g_csmh); bit-identical values.
__global__ void __launch_bounds__(256, 6) k_rows_fwd(const float* __restrict__ csm, int first) {
    int warp = threadIdx.x >> 5, lane = threadIdx.x & 31;
    int row = blockIdx.x * 8 + warp;          // bc*320 + h
    int bc = row / 320, h = row - bc * 320;
    int b = bc >> 4;
    const float2* prow = g_p + b * HW + h * WW;
    float2 v[10];
    if (first) {
        const float2* cn = (const float2*)csm + bc * HW + h * WW;   // natural layout
        uint2* cw = (uint2*)(g_csmh + bc * HW + h * WW);            // paired layout
        #pragma unroll
        for (int t = 0; t < 5; t++) {
            float2 a0 = cn[lane + 64 * t];          // natural j = 2t
            float2 a1 = cn[lane + 64 * t + 32];     // natural j = 2t+1
            unsigned q0 = pack_c(a0), q1 = pack_c(a1);
            cw[lane + 32 * t] = make_uint2(q0, q1);
            float2 cv0 = unpack_c(q0);
            float2 cv1 = unpack_c(q1);
            v[2*t]   = cmul(cv0, prow[lane + 32 * (2*t)]);
            v[2*t+1] = cmul(cv1, prow[lane + 32 * (2*t+1)]);
        }
    } else {
        const uint2* crow2 = (const uint2*)(g_csmh + bc * HW + h * WW);
        #pragma unroll
        for (int t = 0; t < 5; t++) {
            uint2 q = crow2[lane + 32 * t];
            float2 cv0 = unpack_c(q.x);
            float2 cv1 = unpack_c(q.y);
            v[2*t]   = cmul(cv0, prow[lane + 32 * (2*t)]);
            v[2*t+1] = cmul(cv1, prow[lane + 32 * (2*t+1)]);
        }
    }
    fft320_fwd(v, lane);
    uint2* out2 = (uint2*)(g_k + bc * HW + h * WW);
    #pragma unroll
    for (int t = 0; t < 5; t++) {
        uint2 q;
        q.x = pack_c(v[2*t]);
        q.y = pack_c(v[2*t+1]);
        out2[lane + 32 * t] = q;
    }
}

// ---------------- K2: column FFT + fused mask stage + column IFFT (split fp32 SMEM staging) ----------------
__global__ void __launch_bounds__(256) k_cols() {
    __shared__ float sRe[8][324];
    __shared__ float sIm[8][324];
    int bc = blockIdx.x / 40;
    int w0 = (blockIdx.x - bc * 40) * 8;
    int b = bc >> 4;
    __half2* base = g_k + bc * HW;

    for (int pidx = threadIdx.x; pidx < 640; pidx += 256) {
        int h = pidx >> 1, q = pidx & 1;
        uint4 t4 = ((const uint4*)(base + h * WW + w0))[q];
        int c = 4 * q;
        float2 f0 = unpack_c(t4.x), f1 = unpack_c(t4.y);
        float2 f2 = unpack_c(t4.z), f3 = unpack_c(t4.w);
        sRe[c][h]   = f0.x; sIm[c][h]   = f0.y;
        sRe[c+1][h] = f1.x; sIm[c+1][h] = f1.y;
        sRe[c+2][h] = f2.x; sIm[c+2][h] = f2.y;
        sRe[c+3][h] = f3.x; sIm[c+3][h] = f3.y;
    }
    __syncthreads();

    int warp = threadIdx.x >> 5, lane = threadIdx.x & 31;
    float2 v[10];
    #pragma unroll
    for (int j = 0; j < 10; j++) {
        int h = lane + 32 * j;
        v[j] = make_float2(sRe[warp][h], sIm[warp][h]);
    }

    fft320_fwd_t<false>(v, lane);     // skip final m=1 butterfly

    // fused L·M·L stage: v' = P*v + Q*shfl1(v)
    const char2* mrow = g_maskPQ + b * HW + (w0 + warp) * 320;
    #pragma unroll
    for (int j = 0; j < 10; j++) {
        char2 pq = mrow[lane + 32 * j];
        float P = (float)pq.x, Q = (float)pq.y;
        float ox = __shfl_xor_sync(0xffffffffu, v[j].x, 1);
        float oy = __shfl_xor_sync(0xffffffffu, v[j].y, 1);
        v[j] = make_float2(fmaf(Q, ox, P * v[j].x), fmaf(Q, oy, P * v[j].y));
    }

    fft320_inv_t<false>(v, lane);     // skip initial m=1 butterfly

    #pragma unroll
    for (int j = 0; j < 10; j++) {
        int h = lane + 32 * j;
        sRe[warp][h] = v[j].x; sIm[warp][h] = v[j].y;
    }
    __syncthreads();
    for (int pidx = threadIdx.x; pidx < 640; pidx += 256) {
        int h = pidx >> 1, q = pidx & 1;
        int c = 4 * q;
        uint4 t4;
        t4.x = pack_c(make_float2(sRe[c][h],   sIm[c][h]));
        t4.y = pack_c(make_float2(sRe[c+1][h], sIm[c+1][h]));
        t4.z = pack_c(make_float2(sRe[c+2][h], sIm[c+2][h]));
        t4.w = pack_c(make_float2(sRe[c+3][h], sIm[c+3][h]));
        ((uint4*)(base + h * WW + w0))[q] = t4;
    }
}

// ---------------- K3: inverse row FFT + conj(csm) + combine + scale + lam*p ;
//                  last block per batch computes alpha ; last iter skips Ap store ----------------
__global__ void __launch_bounds__(256) k_inv_combine(const float* __restrict__ lam, int lastIt) {
    __shared__ float2 sAcc[8][320];
    int warp = threadIdx.x >> 5, lane = threadIdx.x & 31;
    int b = blockIdx.x / 320, h = blockIdx.x - b * 320;

    float2 acc[10];
    #pragma unroll
    for (int j = 0; j < 10; j++) acc[j] = make_float2(0.f, 0.f);

    #pragma unroll
    for (int cc = 0; cc < 2; cc++) {
        int bc = b * 16 + warp + 8 * cc;
        const uint2* krow2 = (const uint2*)(g_k + bc * HW + h * WW);
        float2 v[10];
        #pragma unroll
        for (int t = 0; t < 5; t++) {
            uint2 q = krow2[lane + 32 * t];
            v[2*t]   = unpack_c(q.x);
            v[2*t+1] = unpack_c(q.y);
        }
        fft320_inv(v, lane);
        const uint2* crow2 = (const uint2*)(g_csmh + bc * HW + h * WW);  // paired
        #pragma unroll
        for (int t = 0; t < 5; t++) {
            uint2 q = crow2[lane + 32 * t];
            float2 cv0 = unpack_c(q.x);
            float2 cv1 = unpack_c(q.y);
            // acc += conj(cv) * v
            acc[2*t].x   += cv0.x * v[2*t].x   + cv0.y * v[2*t].y;
            acc[2*t].y   += cv0.x * v[2*t].y   - cv0.y * v[2*t].x;
            acc[2*t+1].x += cv1.x * v[2*t+1].x + cv1.y * v[2*t+1].y;
            acc[2*t+1].y += cv1.x * v[2*t+1].y - cv1.y * v[2*t+1].x;
        }
    }
    #pragma unroll
    for (int j = 0; j < 10; j++) sAcc[warp][lane + 32 * j] = acc[j];
    __syncthreads();

    const float2* prow = g_p + b * HW + h * WW;
    float2* aprow = g_Ap + b * HW + h * WW;
    float l0 = lam[0];
    float dot = 0.f;
    for (int e = threadIdx.x; e < 320; e += 256) {
        float2 s = make_float2(0.f, 0.f);
        #pragma unroll
        for (int w = 0; w < 8; w++) { s.x += sAcc[w][e].x; s.y += sAcc[w][e].y; }
        float2 pv = prow[e];
        float2 ap = make_float2(s.x * SCALE_N2 + l0 * pv.x, s.y * SCALE_N2 + l0 * pv.y);
        if (!lastIt) aprow[e] = ap;     // Ap only consumed by the r update (dead on last iter)
        dot += pv.x * ap.x + pv.y * ap.y;
    }
    float tot = block_reduce_256(dot);

    __shared__ bool isLast;
    if (threadIdx.x == 0) {
        g_partPA[blockIdx.x] = tot;   // index = b*320 + h
        __threadfence();
        unsigned c = atomicAdd(&g_cntPA[b], 1u);
        isLast = (c == HH - 1);
    }
    __syncthreads();
    if (isLast) {
        float v = 0.f;
        for (int t = threadIdx.x; t < HH; t += 256) v += g_partPA[b * HH + t];
        float s = block_reduce_256(v);
        if (threadIdx.x == 0) {
            g_alpha[b] = g_rTr[b] / s;
            g_cntPA[b] = 0;           // reset for next iteration / replay
        }
    }
}

// ---------------- K4: x += a p ; r -= a Ap ; rr partial ; last block computes beta ----------------
// first: x read skipped (x==0); last: only x+=a*p into outx (r/beta path dead)
__global__ void __launch_bounds__(256) k_update_xr(int first, int last, float* __restrict__ outx) {
    int b = blockIdx.x / UPD_BLKS;
    int blk = blockIdx.x - b * UPD_BLKS;
    float a = g_alpha[b];

    int e4 = b * (HW / 2) + blk * 256 + threadIdx.x;   // float4 index (2 complex)
    const float4* p4  = (const float4*)g_p;
    float4 pv = p4[e4];
    float4 xv;
    if (first) {
        xv = make_float4(a * pv.x, a * pv.y, a * pv.z, a * pv.w);
    } else {
        xv = ((const float4*)g_x)[e4];
        xv.x += a * pv.x; xv.y += a * pv.y; xv.z += a * pv.z; xv.w += a * pv.w;
    }
    if (last) {
        ((float4*)outx)[e4] = xv;
        return;                         // r update, rr reduction, beta all dead on last iter
    }
    ((float4*)g_x)[e4] = xv;

    const float4* ap4 = (const float4*)g_Ap;
    float4* r4 = (float4*)g_r;
    float4 ap = ap4[e4];
    float4 rv = r4[e4];
    rv.x -= a * ap.x; rv.y -= a * ap.y; rv.z -= a * ap.z; rv.w -= a * ap.w;
    r4[e4] = rv;
    float rr = rv.x * rv.x + rv.y * rv.y + rv.z * rv.z + rv.w * rv.w;
    float tot = block_reduce_256(rr);

    __shared__ bool isLast;
    if (threadIdx.x == 0) {
        g_partRR[blockIdx.x] = tot;
        __threadfence();
        unsigned c = atomicAdd(&g_cntRR[b], 1u);
        isLast = (c == UPD_BLKS - 1);
    }
    __syncthreads();
    if (isLast) {
        float v = 0.f;
        for (int t = threadIdx.x; t < UPD_BLKS; t += 256) v += g_partRR[b * UPD_BLKS + t];
        float s = block_reduce_256(v);
        if (threadIdx.x == 0) {
            g_beta[b] = s / g_rTr[b];
            g_rTr[b] = s;
            g_cntRR[b] = 0;
        }
    }
}

// ---------------- K5: p = r + beta p (float4) ----------------
__global__ void __launch_bounds__(256) k_update_p() {
    int b = blockIdx.x / UPD_BLKS;
    int blk = blockIdx.x - b * UPD_BLKS;
    float be = g_beta[b];
    int e4 = b * (HW / 2) + blk * 256 + threadIdx.x;
    const float4* r4 = (const float4*)g_r;
    float4* p4 = (float4*)g_p;
    float4 rv = r4[e4], pv = p4[e4];
    p4[e4] = make_float4(rv.x + be * pv.x, rv.y + be * pv.y,
                         rv.z + be * pv.z, rv.w + be * pv.w);
}

// ---------------- init: p=r=rhs, rr partials ; last block per batch reduces rTr ----------------
__global__ void __launch_bounds__(256) k_init(const float* __restrict__ rhs) {
    int b = blockIdx.x / INIT_BLKS;
    int blk = blockIdx.x - b * INIT_BLKS;
    int i4 = blk * 256 + threadIdx.x;            // [0, 25600): float4 over real plane
    const float4* re4 = (const float4*)(rhs + (2 * b) * HW);
    const float4* im4 = (const float4*)(rhs + (2 * b + 1) * HW);
    float4 re = re4[i4], im = im4[i4];
    float4 lo = make_float4(re.x, im.x, re.y, im.y);
    float4 hi = make_float4(re.z, im.z, re.w, im.w);
    float4* p4 = (float4*)(g_p + b * HW);
    float4* r4 = (float4*)(g_r + b * HW);
    p4[2*i4] = lo; p4[2*i4+1] = hi;
    r4[2*i4] = lo; r4[2*i4+1] = hi;
    float rr = re.x*re.x + re.y*re.y + re.z*re.z + re.w*re.w
             + im.x*im.x + im.y*im.y + im.z*im.z + im.w*im.w;
    float tot = block_reduce_256(rr);

    __shared__ bool isLast;
    if (threadIdx.x == 0) {
        g_partI[blockIdx.x] = tot;
        __threadfence();
        unsigned c = atomicAdd(&g_cntI[b], 1u);
        isLast = (c == INIT_BLKS - 1);
    }
    __syncthreads();
    if (isLast) {
        float v = 0.f;
        for (int t = threadIdx.x; t < INIT_BLKS; t += 256) v += g_partI[b * INIT_BLKS + t];
        float s = block_reduce_256(v);
        if (threadIdx.x == 0) {
            g_rTr[b] = s;
            g_cntI[b] = 0;            // reset for replay
        }
    }
}

// ---------------- launch ----------------
extern "C" void kernel_launch(void* const* d_in, const int* in_sizes, int n_in,
                              void* d_out, int out_size) {
    const float* rhs  = (const float*)d_in[0];
    const float* csm  = (const float*)d_in[1];
    const int*   mask = (const int*)d_in[2];
    const float* lam  = (const float*)d_in[3];
    float* out = (float*)d_out;

    const int FG = BATCH * NC * HH / 8;   // 5120
    const int CG = BATCH * NC * (WW / 8); // 5120
    const int IG = BATCH * HH;            // 2560
    const int UG = BATCH * UPD_BLKS;      // 1600

    k_twinit<<<2, 256>>>();
    k_maskprep<<<BATCH * HW / 256, 256>>>(mask);
    k_init<<<BATCH * INIT_BLKS, 256>>>(rhs);

    for (int it = 0; it < NITER; it++) {
        int lastIt = (it == NITER - 1) ? 1 : 0;
        k_rows_fwd<<<FG, 256>>>(csm, it == 0 ? 1 : 0);
        k_cols<<<CG, 256>>>();
        k_inv_combine<<<IG, 256>>>(lam, lastIt);
        k_update_xr<<<UG, 256>>>(it == 0 ? 1 : 0, lastIt, out);
        if (!lastIt) k_update_p<<<UG, 256>>>();
    }
}